// round 13
// baseline (speedup 1.0000x reference)
#include <cuda_runtime.h>

// ---------------------------------------------------------------------------
// Static scratch (sanctioned workaround for no-alloc rule)
// ---------------------------------------------------------------------------
#define NMAX 250112  // >= 250000, multiple of 64
#define GP_BLOCKS 912   // 152 SMs x 6 blocks

__device__ __align__(256) float g_X  [(size_t)NMAX * 64];
__device__ __align__(256) float g_F1 [(size_t)NMAX * 64];
__device__ __align__(256) float g_F2a[(size_t)NMAX * 32];
__device__ __align__(256) float g_F2b[(size_t)NMAX * 32];
__device__ __align__(256) float g_A8 [(size_t)NMAX * 8];
__device__ __align__(256) float g_T8 [(size_t)NMAX * 8];
__device__ int  g_cnt1[27];
__device__ int  g_cntd[8];
__device__ __align__(256) int2 g_pairs1[(size_t)27 * NMAX];
__device__ __align__(256) int2 g_pairsd[(size_t)8  * NMAX];
__device__ __align__(256) int  g_idxT [(size_t)27 * NMAX];

typedef unsigned long long u64;

// ---------------------------------------------------------------------------
// Packed f32x2 helpers (SASS FFMA2 — only reachable via PTX fma.rn.f32x2)
// ---------------------------------------------------------------------------
__device__ __forceinline__ u64 pack2(float a, float b) {
    u64 r;
    asm("mov.b64 %0, {%1, %2};" : "=l"(r) : "f"(a), "f"(b));
    return r;
}
__device__ __forceinline__ void unpack2(u64 v, float& a, float& b) {
    asm("mov.b64 {%0, %1}, %2;" : "=f"(a), "=f"(b) : "l"(v));
}
__device__ __forceinline__ u64 fma2(u64 a, u64 b, u64 c) {
    u64 d;
    asm("fma.rn.f32x2 %0, %1, %2, %3;" : "=l"(d) : "l"(a), "l"(b), "l"(c));
    return d;
}
__device__ __forceinline__ u64 add2(u64 a, u64 b) {
    u64 d;
    asm("add.rn.f32x2 %0, %1, %2;" : "=l"(d) : "l"(a), "l"(b));
    return d;
}

// ---------------------------------------------------------------------------
// Vector reduction helper (sm_90+): one LTS request for 4 channels
// ---------------------------------------------------------------------------
__device__ __forceinline__ void red_add_v4(float* p, float4 v) {
    asm volatile("red.global.add.v4.f32 [%0], {%1, %2, %3, %4};"
                 :: "l"(p), "f"(v.x), "f"(v.y), "f"(v.z), "f"(v.w)
                 : "memory");
}

// ---------------------------------------------------------------------------
// Elementwise helpers (k_add also zeroes the pair counters: saves a launch)
// ---------------------------------------------------------------------------
__global__ void k_add(const float4* __restrict__ a, const float4* __restrict__ b,
                      float4* __restrict__ o, int n4) {
    if (blockIdx.x == 0) {
        if (threadIdx.x < 27) g_cnt1[threadIdx.x] = 0;
        if (threadIdx.x >= 32 && threadIdx.x < 40) g_cntd[threadIdx.x - 32] = 0;
    }
    int t = blockIdx.x * blockDim.x + threadIdx.x;
    if (t < n4) {
        float4 x = a[t], y = b[t];
        o[t] = make_float4(x.x + y.x, x.y + y.y, x.z + y.z, x.w + y.w);
    }
}

__global__ void k_bias_init32(float* __restrict__ buf, const float* __restrict__ b, int n) {
    int t = blockIdx.x * blockDim.x + threadIdx.x;
    if (t < n) buf[t] = b[t & 31];
}

__global__ void k_relu(float* __restrict__ buf, int n) {
    int t = blockIdx.x * blockDim.x + threadIdx.x;
    if (t < n) buf[t] = fmaxf(buf[t], 0.0f);
}

// ---------------------------------------------------------------------------
// idx2 transpose: [N,27] -> [27][N] for coalesced per-k index loads.
// ---------------------------------------------------------------------------
__global__ void k_tidx(const int* __restrict__ idx2, int* __restrict__ idxT, int N) {
    __shared__ int tile[64 * 27];
    int base = blockIdx.x * 64;
    int npts = N - base; if (npts > 64) npts = 64;
    int tot = npts * 27;
    for (int e = threadIdx.x; e < tot; e += blockDim.x)
        tile[e] = idx2[(size_t)base * 27 + e];
    __syncthreads();
    for (int e = threadIdx.x; e < 27 * 64; e += blockDim.x) {
        int k = e >> 6, ii = e & 63;
        if (ii < npts) idxT[(size_t)k * N + base + ii] = tile[ii * 27 + k];
    }
}

// ---------------------------------------------------------------------------
// Pair-list construction with BLOCK-AGGREGATED atomics.
// ---------------------------------------------------------------------------
__global__ void k_build1(const int* __restrict__ idx, int total) {  // total = N*27
    __shared__ int scnt[27];
    __shared__ int sbase[27];
    int tid = threadIdx.x;
    if (tid < 27) scnt[tid] = 0;
    __syncthreads();

    int t = blockIdx.x * blockDim.x + tid;
    int k = -1, i = 0, j = 0, rank = 0;
    if (t < total) {
        int kk = t % 27;
        if (kk != 13) {                 // center offset handled densely
            int jj = idx[t];
            if (jj >= 0) {
                k = kk; j = jj; i = t / 27;
                rank = atomicAdd(&scnt[k], 1);
            }
        }
    }
    __syncthreads();
    if (tid < 27 && scnt[tid] > 0)
        sbase[tid] = atomicAdd(&g_cnt1[tid], scnt[tid]);
    __syncthreads();
    if (k >= 0)
        g_pairs1[(size_t)k * NMAX + sbase[k] + rank] = make_int2(i, j);
}

__global__ void k_buildd(const int* __restrict__ idx, int total) {  // total = N2*8
    __shared__ int scnt[8];
    __shared__ int sbase[8];
    int tid = threadIdx.x;
    if (tid < 8) scnt[tid] = 0;
    __syncthreads();

    int t = blockIdx.x * blockDim.x + tid;
    int k = -1, i = 0, j = 0, rank = 0;
    if (t < total) {
        int jj = idx[t];
        if (jj >= 0) {
            k = t % 8; j = jj; i = t / 8;
            rank = atomicAdd(&scnt[k], 1);
        }
    }
    __syncthreads();
    if (tid < 8 && scnt[tid] > 0)
        sbase[tid] = atomicAdd(&g_cntd[tid], scnt[tid]);
    __syncthreads();
    if (k >= 0)
        g_pairsd[(size_t)k * NMAX + sbase[k] + rank] = make_int2(i, j);
}

// ---------------------------------------------------------------------------
// conv1 center offset (k==13, identity map): F1 = X @ W13 + b1  (dense GEMM)
// ---------------------------------------------------------------------------
__global__ void k_conv1_center(const float* __restrict__ W, const float* __restrict__ b1,
                               const float* __restrict__ src, float* __restrict__ dst, int N) {
    __shared__ __align__(16) float xs[64][68];
    __shared__ __align__(16) float ws[64][68];
    int tid = threadIdx.x;
    int base = blockIdx.x * 64;

    const float4* W4 = (const float4*)(W + 13 * 4096);
    for (int f = tid; f < 1024; f += 256) {
        int c = f >> 4, oq = f & 15;
        *(float4*)&ws[c][oq * 4] = W4[f];
    }
    int r = tid & 63, cg = tid >> 6;
#pragma unroll
    for (int m = 0; m < 4; m++) {
        int cc = cg * 4 + m;
        float4 v = make_float4(0.f, 0.f, 0.f, 0.f);
        if (base + r < N) v = ((const float4*)src)[(size_t)(base + r) * 16 + cc];
        xs[cc * 4 + 0][r] = v.x; xs[cc * 4 + 1][r] = v.y;
        xs[cc * 4 + 2][r] = v.z; xs[cc * 4 + 3][r] = v.w;
    }
    __syncthreads();

    int p0 = (tid & 15) * 4, o0 = (tid >> 4) * 4;
    u64 acc2[4][2] = {};
#pragma unroll 8
    for (int c = 0; c < 64; c++) {
        float4 a = *(float4*)&xs[c][p0];
        u64 w01 = *(const u64*)&ws[c][o0];
        u64 w23 = *(const u64*)&ws[c][o0 + 2];
        float ap[4] = {a.x, a.y, a.z, a.w};
#pragma unroll
        for (int p = 0; p < 4; p++) {
            u64 ad = pack2(ap[p], ap[p]);
            acc2[p][0] = fma2(ad, w01, acc2[p][0]);
            acc2[p][1] = fma2(ad, w23, acc2[p][1]);
        }
    }
    float4 bb = ((const float4*)b1)[o0 >> 2];
#pragma unroll
    for (int p = 0; p < 4; p++) {
        int i = base + p0 + p;
        if (i < N) {
            float a0, a1, a2, a3;
            unpack2(acc2[p][0], a0, a1);
            unpack2(acc2[p][1], a2, a3);
            float4 o = make_float4(a0 + bb.x, a1 + bb.y, a2 + bb.z, a3 + bb.w);
            ((float4*)dst)[(size_t)i * 16 + (o0 >> 2)] = o;
        }
    }
}

// ---------------------------------------------------------------------------
// PERSISTENT pair-compacted gather-GEMM. PIPE selects register-prefetch
// software pipelining (good for COUT=64's long compute body; bad for COUT=32).
// ---------------------------------------------------------------------------
template <int COUT, int NK, bool RELU_SRC, bool PIPE>
__global__ void __launch_bounds__(128, 4)
k_pair_gemm_p(const float* __restrict__ W, const int2* __restrict__ pairsBase,
              const int* __restrict__ cntArr,
              const float* __restrict__ src, float* __restrict__ dst) {
    constexpr int CT = COUT / 8;          // couts per thread: 64->8, 32->4
    __shared__ __align__(16) float xs[64][68];
    __shared__ __align__(16) float ws[64][COUT + 4];
    __shared__ int sdst[64];
    __shared__ int ssrc[64];
    __shared__ int spre[NK + 1];
    __shared__ int scnt[NK];

    int tid = threadIdx.x;
    if (tid < NK) scnt[tid] = cntArr[tid];
    __syncthreads();
    if (tid == 0) {
        int s = 0;
        for (int k = 0; k < NK; k++) { spre[k] = s; s += (scnt[k] + 63) >> 6; }
        spre[NK] = s;
    }
    __syncthreads();

    int total = spre[NK];
    int chunk = (total + gridDim.x - 1) / gridDim.x;
    int tile  = blockIdx.x * chunk;
    int tEnd  = min(tile + chunk, total);
    if (tile >= tEnd) return;

    int pg = tid & 15, og = tid >> 4;     // 16 pair-groups x 8 chan-groups
    int p0 = pg * 4, o0 = og * CT;
    int row0 = tid >> 2, cl = tid & 3;    // gather rows row0, row0+32

    int kcur = 0;
    while (spre[kcur + 1] <= tile) kcur++;
    int kprev = -1;

    if (PIPE) {
        float4 v0[4], v1[4];
        int dpre;
        {
            int t0 = (tile - spre[kcur]) * 64;
            int n  = scnt[kcur];
            const int2* pb = pairsBase + (size_t)kcur * NMAX + t0;
            int j0 = (t0 + row0      < n) ? pb[row0].y      : -1;
            int j1 = (t0 + row0 + 32 < n) ? pb[row0 + 32].y : -1;
            dpre = (tid < 64 && t0 + tid < n) ? pb[tid].x : -1;
            const float4* s0 = (j0 >= 0) ? ((const float4*)src) + (size_t)j0 * 16 : nullptr;
            const float4* s1 = (j1 >= 0) ? ((const float4*)src) + (size_t)j1 * 16 : nullptr;
#pragma unroll
            for (int m = 0; m < 4; m++) {
                int col = cl + m * 4;
                float4 a = make_float4(0.f, 0.f, 0.f, 0.f), bb = a;
                if (s0) a  = s0[col];
                if (s1) bb = s1[col];
                v0[m] = a; v1[m] = bb;
            }
        }

        for (;;) {
            __syncthreads();
            if (kcur != kprev) {
                const float4* W4 = (const float4*)(W + (size_t)kcur * 64 * COUT);
                for (int f = tid; f < 64 * COUT / 4; f += 128) {
                    int c = f / (COUT / 4), oq = f % (COUT / 4);
                    *(float4*)&ws[c][oq * 4] = W4[f];
                }
                kprev = kcur;
            }
#pragma unroll
            for (int m = 0; m < 4; m++) {
                int c = (cl + m * 4) * 4;
                xs[c + 0][row0] = v0[m].x; xs[c + 1][row0] = v0[m].y;
                xs[c + 2][row0] = v0[m].z; xs[c + 3][row0] = v0[m].w;
                xs[c + 0][row0 + 32] = v1[m].x; xs[c + 1][row0 + 32] = v1[m].y;
                xs[c + 2][row0 + 32] = v1[m].z; xs[c + 3][row0 + 32] = v1[m].w;
            }
            if (tid < 64) sdst[tid] = dpre;
            __syncthreads();

            int tnext = tile + 1;
            bool more = (tnext < tEnd);
            int knext = kcur;
            if (more) {
                while (spre[knext + 1] <= tnext) knext++;
                int t0 = (tnext - spre[knext]) * 64;
                int n  = scnt[knext];
                const int2* pb = pairsBase + (size_t)knext * NMAX + t0;
                int j0 = (t0 + row0      < n) ? pb[row0].y      : -1;
                int j1 = (t0 + row0 + 32 < n) ? pb[row0 + 32].y : -1;
                dpre = (tid < 64 && t0 + tid < n) ? pb[tid].x : -1;
                const float4* s0 = (j0 >= 0) ? ((const float4*)src) + (size_t)j0 * 16 : nullptr;
                const float4* s1 = (j1 >= 0) ? ((const float4*)src) + (size_t)j1 * 16 : nullptr;
#pragma unroll
                for (int m = 0; m < 4; m++) {
                    int col = cl + m * 4;
                    float4 a = make_float4(0.f, 0.f, 0.f, 0.f), bb = a;
                    if (s0) a  = s0[col];
                    if (s1) bb = s1[col];
                    v0[m] = a; v1[m] = bb;
                }
            }

            u64 acc2[4][CT / 2] = {};
#pragma unroll 8
            for (int c = 0; c < 64; c++) {
                u64 wq[CT / 2];
                if (CT == 8) {
                    ulonglong2 wA = *(const ulonglong2*)&ws[c][o0];
                    ulonglong2 wB = *(const ulonglong2*)&ws[c][o0 + 4];
                    wq[0] = wA.x; wq[1] = wA.y; wq[2] = wB.x; wq[3] = wB.y;
                } else {
                    ulonglong2 wA = *(const ulonglong2*)&ws[c][o0];
                    wq[0] = wA.x; wq[1] = wA.y;
                }
                float4 a4 = *(float4*)&xs[c][p0];
                float a[4] = {a4.x, a4.y, a4.z, a4.w};
#pragma unroll
                for (int p = 0; p < 4; p++) {
                    u64 ad = pack2(a[p], a[p]);
#pragma unroll
                    for (int q = 0; q < CT / 2; q++)
                        acc2[p][q] = fma2(ad, wq[q], acc2[p][q]);
                }
            }
#pragma unroll
            for (int p = 0; p < 4; p++) {
                int d = sdst[p0 + p];
                if (d >= 0) {
#pragma unroll
                    for (int h = 0; h < CT / 4; h++) {
                        float4 v;
                        unpack2(acc2[p][h * 2 + 0], v.x, v.y);
                        unpack2(acc2[p][h * 2 + 1], v.z, v.w);
                        red_add_v4(&dst[(size_t)d * COUT + o0 + h * 4], v);
                    }
                }
            }

            if (!more) break;
            tile = tnext; kcur = knext;
        }
    } else {
        for (; tile < tEnd; ++tile) {
            while (spre[kcur + 1] <= tile) kcur++;

            __syncthreads();
            if (kcur != kprev) {
                const float4* W4 = (const float4*)(W + (size_t)kcur * 64 * COUT);
                for (int f = tid; f < 64 * COUT / 4; f += 128) {
                    int c = f / (COUT / 4), oq = f % (COUT / 4);
                    *(float4*)&ws[c][oq * 4] = W4[f];
                }
                kprev = kcur;
            }
            int t0 = (tile - spre[kcur]) * 64;
            int n  = scnt[kcur];
            if (tid < 64) {
                int2 pr = make_int2(-1, -1);
                if (t0 + tid < n) pr = pairsBase[(size_t)kcur * NMAX + t0 + tid];
                sdst[tid] = pr.x; ssrc[tid] = pr.y;
            }
            __syncthreads();

#pragma unroll
            for (int pass = 0; pass < 2; pass++) {
                int row = row0 + pass * 32;
                int j = ssrc[row];
                const float4* srow = (j >= 0) ? ((const float4*)src) + (size_t)j * 16 : nullptr;
#pragma unroll
                for (int m = 0; m < 4; m++) {
                    int col = cl + m * 4;
                    float4 v = make_float4(0.f, 0.f, 0.f, 0.f);
                    if (srow) v = srow[col];
                    if (RELU_SRC) {
                        v.x = fmaxf(v.x, 0.f); v.y = fmaxf(v.y, 0.f);
                        v.z = fmaxf(v.z, 0.f); v.w = fmaxf(v.w, 0.f);
                    }
                    int c = col * 4;
                    xs[c + 0][row] = v.x; xs[c + 1][row] = v.y;
                    xs[c + 2][row] = v.z; xs[c + 3][row] = v.w;
                }
            }
            __syncthreads();

            u64 acc2[4][CT / 2] = {};
#pragma unroll 8
            for (int c = 0; c < 64; c++) {
                u64 wq[CT / 2];
                if (CT == 8) {
                    ulonglong2 wA = *(const ulonglong2*)&ws[c][o0];
                    ulonglong2 wB = *(const ulonglong2*)&ws[c][o0 + 4];
                    wq[0] = wA.x; wq[1] = wA.y; wq[2] = wB.x; wq[3] = wB.y;
                } else {
                    ulonglong2 wA = *(const ulonglong2*)&ws[c][o0];
                    wq[0] = wA.x; wq[1] = wA.y;
                }
                float4 a4 = *(float4*)&xs[c][p0];
                float a[4] = {a4.x, a4.y, a4.z, a4.w};
#pragma unroll
                for (int p = 0; p < 4; p++) {
                    u64 ad = pack2(a[p], a[p]);
#pragma unroll
                    for (int q = 0; q < CT / 2; q++)
                        acc2[p][q] = fma2(ad, wq[q], acc2[p][q]);
                }
            }
#pragma unroll
            for (int p = 0; p < 4; p++) {
                int d = sdst[p0 + p];
                if (d >= 0) {
#pragma unroll
                    for (int h = 0; h < CT / 4; h++) {
                        float4 v;
                        unpack2(acc2[p][h * 2 + 0], v.x, v.y);
                        unpack2(acc2[p][h * 2 + 1], v.z, v.w);
                        red_add_v4(&dst[(size_t)d * COUT + o0 + h * 4], v);
                    }
                }
            }
        }
    }
}

// ---------------------------------------------------------------------------
// Warp-split 27-offset conv, CIN=32 -> COUT=8.
// ROUND-13: 2 points per thread (was 4) -> acc/fr register count halved,
// occupancy rises from ~5 to the smem-limited 8 blocks/SM. 2x blocks.
// ---------------------------------------------------------------------------
template <bool RELU>
__global__ void __launch_bounds__(128)
k_conv27W(const float* __restrict__ feat, const int* __restrict__ idxT,
          const float* __restrict__ W, const float* __restrict__ b,
          float* __restrict__ out, int N) {
    __shared__ __align__(16) u64 wsm[27 * 8 * 4 * 4];  // 3456 u64 = 27.6 KB
    __shared__ float sbv[8];
    int tid = threadIdx.x;

    for (int f = tid; f < 3456; f += 128) {
        int k = f >> 7, r = f & 127;
        int cc = r >> 4, q = (r >> 2) & 3, op = r & 3;
        float2 w2 = *(const float2*)&W[k * 256 + (q * 8 + cc) * 8 + op * 2];
        wsm[f] = pack2(w2.x, w2.y);
    }
    if (tid < 8) sbv[tid] = b[tid];
    __syncthreads();

    int q = tid & 3, pb = tid >> 2;
    int i0 = blockIdx.x * 64 + pb;       // points i0, i0+32

    u64 acc[2][4] = {};

    for (int k = 0; k < 27; k++) {
        const int* ik = idxT + (size_t)k * N;
        int j[2];
#pragma unroll
        for (int p = 0; p < 2; p++) {
            int i = i0 + p * 32;
            j[p] = (i < N) ? ik[i] : -1;
        }
        bool any = (j[0] >= 0) | (j[1] >= 0);
        if (__ballot_sync(0xFFFFFFFFu, any) == 0) continue;

        float fr[2][8];
#pragma unroll
        for (int p = 0; p < 2; p++) {
            float4 A = make_float4(0.f, 0.f, 0.f, 0.f), B = A;
            if (j[p] >= 0) {
                const float4* fp = (const float4*)(feat + (size_t)j[p] * 32 + q * 8);
                A = fp[0]; B = fp[1];
            }
            fr[p][0] = A.x; fr[p][1] = A.y; fr[p][2] = A.z; fr[p][3] = A.w;
            fr[p][4] = B.x; fr[p][5] = B.y; fr[p][6] = B.z; fr[p][7] = B.w;
        }

        const u64* wkq = wsm + k * 128 + q * 4;
#pragma unroll
        for (int cc = 0; cc < 8; cc++) {
            const ulonglong2* wp = (const ulonglong2*)(wkq + cc * 16);
            ulonglong2 wA = wp[0];          // out pairs (0,1),(2,3)
            ulonglong2 wB = wp[1];          // out pairs (4,5),(6,7)
#pragma unroll
            for (int p = 0; p < 2; p++) {
                u64 ad = pack2(fr[p][cc], fr[p][cc]);
                acc[p][0] = fma2(ad, wA.x, acc[p][0]);
                acc[p][1] = fma2(ad, wA.y, acc[p][1]);
                acc[p][2] = fma2(ad, wB.x, acc[p][2]);
                acc[p][3] = fma2(ad, wB.y, acc[p][3]);
            }
        }
    }

    // reduce across the 4 q-lanes of each point (consecutive lanes)
#pragma unroll
    for (int p = 0; p < 2; p++) {
#pragma unroll
        for (int m = 0; m < 4; m++) {
            u64 o1 = __shfl_down_sync(0xFFFFFFFFu, acc[p][m], 1, 4);
            acc[p][m] = add2(acc[p][m], o1);
            u64 o2 = __shfl_down_sync(0xFFFFFFFFu, acc[p][m], 2, 4);
            acc[p][m] = add2(acc[p][m], o2);
        }
    }

    if (q == 0) {
#pragma unroll
        for (int p = 0; p < 2; p++) {
            int i = i0 + p * 32;
            if (i < N) {
                float t[8];
                unpack2(acc[p][0], t[0], t[1]);
                unpack2(acc[p][1], t[2], t[3]);
                unpack2(acc[p][2], t[4], t[5]);
                unpack2(acc[p][3], t[6], t[7]);
#pragma unroll
                for (int o = 0; o < 8; o++) {
                    float x = t[o] + sbv[o];
                    if (RELU) x = fmaxf(x, 0.0f);
                    t[o] = x;
                }
                float* op = out + (size_t)i * 8;
                ((float4*)op)[0] = make_float4(t[0], t[1], t[2], t[3]);
                ((float4*)op)[1] = make_float4(t[4], t[5], t[6], t[7]);
            }
        }
    }
}

// ---------------------------------------------------------------------------
// Dense-k 27-offset conv, small CIN (=8) — round-3 proven per-point form.
// ---------------------------------------------------------------------------
template <int CIN, int COUT, int PT, bool RELU, bool RES>
__global__ void k_conv27(const float* __restrict__ feat, const int* __restrict__ idx,
                         const float* __restrict__ W, const float* __restrict__ b,
                         const float* __restrict__ res, float* __restrict__ out,
                         int outStride, int outOff, int N) {
    __shared__ __align__(16) float ws[27 * CIN * COUT];
    __shared__ float sb[COUT];
    int tid = threadIdx.x;
    for (int f = tid; f < 27 * CIN * COUT; f += blockDim.x) ws[f] = W[f];
    if (tid < COUT) sb[tid] = b[tid];
    __syncthreads();

    int i0 = (blockIdx.x * blockDim.x + tid) * PT;

    u64 acc[PT][COUT / 2] = {};

    for (int k = 0; k < 27; k++) {
        int jj[PT];
#pragma unroll
        for (int p = 0; p < PT; p++) {
            int i = i0 + p;
            jj[p] = (i < N) ? idx[(size_t)i * 27 + k] : -1;
        }
        const float* wk = &ws[k * CIN * COUT];
#pragma unroll
        for (int c4 = 0; c4 < CIN / 4; c4++) {
            float vv[PT][4];
#pragma unroll
            for (int p = 0; p < PT; p++) {
                float4 v = make_float4(0.f, 0.f, 0.f, 0.f);
                if (jj[p] >= 0) v = ((const float4*)feat)[(size_t)jj[p] * (CIN / 4) + c4];
                vv[p][0] = v.x; vv[p][1] = v.y; vv[p][2] = v.z; vv[p][3] = v.w;
            }
#pragma unroll
            for (int cc = 0; cc < 4; cc++) {
                const u64* w2 = (const u64*)&wk[(c4 * 4 + cc) * COUT];
                u64 wq[COUT / 2];
#pragma unroll
                for (int qq = 0; qq < COUT / 2; qq++) wq[qq] = w2[qq];
#pragma unroll
                for (int p = 0; p < PT; p++) {
                    u64 ad = pack2(vv[p][cc], vv[p][cc]);
#pragma unroll
                    for (int qq = 0; qq < COUT / 2; qq++)
                        acc[p][qq] = fma2(ad, wq[qq], acc[p][qq]);
                }
            }
        }
    }

#pragma unroll
    for (int p = 0; p < PT; p++) {
        int i = i0 + p;
        if (i < N) {
            float tmp[COUT];
#pragma unroll
            for (int qq = 0; qq < COUT / 2; qq++)
                unpack2(acc[p][qq], tmp[2 * qq], tmp[2 * qq + 1]);
#pragma unroll
            for (int o = 0; o < COUT; o++) {
                float x = tmp[o] + sb[o];
                if (RELU) x = fmaxf(x, 0.0f);
                tmp[o] = x;
            }
            float* op = out + (size_t)i * outStride + outOff;
            const float* rp = RES ? (res + (size_t)i * 32 + outOff) : nullptr;
#pragma unroll
            for (int qq = 0; qq < COUT / 4; qq++) {
                float4 t4 = make_float4(tmp[qq * 4 + 0], tmp[qq * 4 + 1],
                                        tmp[qq * 4 + 2], tmp[qq * 4 + 3]);
                if (RES) {
                    float4 r4 = ((const float4*)rp)[qq];
                    t4.x += r4.x; t4.y += r4.y; t4.z += r4.z; t4.w += r4.w;
                }
                ((float4*)op)[qq] = t4;
            }
        }
    }
}

// ---------------------------------------------------------------------------
// FUSED conv27 (8->8, relu) + pointwise (8->16) + bias + residual (EPILOGUE
// fusion only — loop body identical to proven k_conv27<8,8,PT>):
//   Fn[i, 16:32] = relu(conv27(T8, W11)+B11) @ W12 + B12 + F[i, 16:32]
// ---------------------------------------------------------------------------
template <int PT>
__global__ void k_conv27_pw8(const float* __restrict__ feat, const int* __restrict__ idx,
                             const float* __restrict__ W, const float* __restrict__ b,
                             const float* __restrict__ W12, const float* __restrict__ b12,
                             const float* __restrict__ res, float* __restrict__ out, int N) {
    __shared__ __align__(16) float ws[27 * 64];      // 27x8x8 conv weights
    __shared__ __align__(16) u64 w12p[64];           // 8x16 pw weights, paired
    __shared__ float sb[8];
    __shared__ float sb12[16];
    int tid = threadIdx.x;
    for (int f = tid; f < 27 * 64; f += blockDim.x) ws[f] = W[f];
    if (tid < 64) {
        int c = tid >> 3, op = tid & 7;
        float2 w2 = *(const float2*)&W12[c * 16 + op * 2];
        w12p[tid] = pack2(w2.x, w2.y);
    }
    if (tid < 8)  sb[tid] = b[tid];
    if (tid < 16) sb12[tid] = b12[tid];
    __syncthreads();

    int i0 = (blockIdx.x * blockDim.x + tid) * PT;

    u64 acc[PT][4] = {};

    for (int k = 0; k < 27; k++) {
        int jj[PT];
#pragma unroll
        for (int p = 0; p < PT; p++) {
            int i = i0 + p;
            jj[p] = (i < N) ? idx[(size_t)i * 27 + k] : -1;
        }
        const float* wk = &ws[k * 64];
#pragma unroll
        for (int c4 = 0; c4 < 2; c4++) {
            float vv[PT][4];
#pragma unroll
            for (int p = 0; p < PT; p++) {
                float4 v = make_float4(0.f, 0.f, 0.f, 0.f);
                if (jj[p] >= 0) v = ((const float4*)feat)[(size_t)jj[p] * 2 + c4];
                vv[p][0] = v.x; vv[p][1] = v.y; vv[p][2] = v.z; vv[p][3] = v.w;
            }
#pragma unroll
            for (int cc = 0; cc < 4; cc++) {
                const u64* w2 = (const u64*)&wk[(c4 * 4 + cc) * 8];
                u64 wq[4];
#pragma unroll
                for (int qq = 0; qq < 4; qq++) wq[qq] = w2[qq];
#pragma unroll
                for (int p = 0; p < PT; p++) {
                    u64 ad = pack2(vv[p][cc], vv[p][cc]);
#pragma unroll
                    for (int qq = 0; qq < 4; qq++)
                        acc[p][qq] = fma2(ad, wq[qq], acc[p][qq]);
                }
            }
        }
    }

#pragma unroll
    for (int p = 0; p < PT; p++) {
        int i = i0 + p;
        if (i < N) {
            float tmp[8];
#pragma unroll
            for (int qq = 0; qq < 4; qq++)
                unpack2(acc[p][qq], tmp[2 * qq], tmp[2 * qq + 1]);
#pragma unroll
            for (int o = 0; o < 8; o++)
                tmp[o] = fmaxf(tmp[o] + sb[o], 0.0f);

            // pointwise 8->16 (epilogue registers only)
            u64 opw[8] = {};
#pragma unroll
            for (int cc = 0; cc < 8; cc++) {
                u64 ad = pack2(tmp[cc], tmp[cc]);
                const u64* wrow = w12p + cc * 8;
#pragma unroll
                for (int jq = 0; jq < 8; jq++)
                    opw[jq] = fma2(ad, wrow[jq], opw[jq]);
            }
            float o16[16];
#pragma unroll
            for (int jq = 0; jq < 8; jq++)
                unpack2(opw[jq], o16[2 * jq], o16[2 * jq + 1]);

            float* op = out + (size_t)i * 32 + 16;
            const float* rp = res + (size_t)i * 32 + 16;
#pragma unroll
            for (int qq = 0; qq < 4; qq++) {
                float4 r4 = ((const float4*)rp)[qq];
                float4 t4 = make_float4(o16[qq * 4 + 0] + sb12[qq * 4 + 0] + r4.x,
                                        o16[qq * 4 + 1] + sb12[qq * 4 + 1] + r4.y,
                                        o16[qq * 4 + 2] + sb12[qq * 4 + 2] + r4.z,
                                        o16[qq * 4 + 3] + sb12[qq * 4 + 3] + r4.w);
                ((float4*)op)[qq] = t4;
            }
        }
    }
}

// ---------------------------------------------------------------------------
// Pointwise (kernel-size-1) conv: out = (relu?)(feat @ W + b) (+ res)
// ---------------------------------------------------------------------------
template <int CIN, int COUT, bool RELU, bool RES>
__global__ void k_pw(const float* __restrict__ feat, const float* __restrict__ W,
                     const float* __restrict__ b, const float* __restrict__ res,
                     float* __restrict__ out, int outStride, int outOff, int N) {
    __shared__ __align__(16) float ws[CIN * COUT];
    __shared__ float sb[COUT];
    int tid = threadIdx.x;
    for (int f = tid; f < CIN * COUT; f += blockDim.x) ws[f] = W[f];
    if (tid < COUT) sb[tid] = b[tid];
    __syncthreads();

    int i = blockIdx.x * blockDim.x + tid;
    if (i >= N) return;

    u64 acc[COUT / 2] = {};

#pragma unroll
    for (int c4 = 0; c4 < CIN / 4; c4++) {
        float4 v = ((const float4*)feat)[(size_t)i * (CIN / 4) + c4];
        float vv[4] = {v.x, v.y, v.z, v.w};
#pragma unroll
        for (int cc = 0; cc < 4; cc++) {
            const u64* w2 = (const u64*)&ws[(c4 * 4 + cc) * COUT];
            u64 ad = pack2(vv[cc], vv[cc]);
#pragma unroll
            for (int qq = 0; qq < COUT / 2; qq++)
                acc[qq] = fma2(ad, w2[qq], acc[qq]);
        }
    }

    float tmp[COUT];
#pragma unroll
    for (int qq = 0; qq < COUT / 2; qq++)
        unpack2(acc[qq], tmp[2 * qq], tmp[2 * qq + 1]);

    float* op = out + (size_t)i * outStride + outOff;
#pragma unroll
    for (int qq = 0; qq < COUT / 4; qq++) {
        float4 t4 = make_float4(tmp[qq * 4 + 0] + sb[qq * 4 + 0], tmp[qq * 4 + 1] + sb[qq * 4 + 1],
                                tmp[qq * 4 + 2] + sb[qq * 4 + 2], tmp[qq * 4 + 3] + sb[qq * 4 + 3]);
        if (RELU) {
            t4.x = fmaxf(t4.x, 0.f); t4.y = fmaxf(t4.y, 0.f);
            t4.z = fmaxf(t4.z, 0.f); t4.w = fmaxf(t4.w, 0.f);
        }
        if (RES) {
            float4 r4 = ((const float4*)(res + (size_t)i * 32 + outOff))[qq];
            t4.x += r4.x; t4.y += r4.y; t4.z += r4.z; t4.w += r4.w;
        }
        ((float4*)op)[qq] = t4;
    }
}

// ---------------------------------------------------------------------------
// Host launcher
// ---------------------------------------------------------------------------
extern "C" void kernel_launch(void* const* d_in, const int* in_sizes, int n_in,
                              void* d_out, int out_size) {
    const float* x_feat = (const float*)d_in[0];
    const float* f1_ref = (const float*)d_in[1];
    const float* w1     = (const float*)d_in[2];
    const float* b1     = (const float*)d_in[3];
    const float* wd     = (const float*)d_in[4];
    const float* bd     = (const float*)d_in[5];
    const float* rw00   = (const float*)d_in[6];
    const float* rb00   = (const float*)d_in[7];
    const float* rw01   = (const float*)d_in[8];
    const float* rb01   = (const float*)d_in[9];
    const float* rw10   = (const float*)d_in[10];
    const float* rb10   = (const float*)d_in[11];
    const float* rw11   = (const float*)d_in[12];
    const float* rb11   = (const float*)d_in[13];
    const float* rw12   = (const float*)d_in[14];
    const float* rb12   = (const float*)d_in[15];
    const float* w4     = (const float*)d_in[16];
    const float* b4     = (const float*)d_in[17];
    const int*   idx1   = (const int*)d_in[18];
    const int*   idxd   = (const int*)d_in[19];
    const int*   idx2   = (const int*)d_in[20];
    float* outp = (float*)d_out;

    int N  = in_sizes[0] / 64;
    int N2 = in_sizes[19] / 8;

    float *pX, *pF1, *pF2a, *pF2b, *pA8, *pT8;
    int *pCnt1, *pCntd, *pIdxT;
    int2 *pPairs1, *pPairsd;
    cudaGetSymbolAddress((void**)&pX, g_X);
    cudaGetSymbolAddress((void**)&pF1, g_F1);
    cudaGetSymbolAddress((void**)&pF2a, g_F2a);
    cudaGetSymbolAddress((void**)&pF2b, g_F2b);
    cudaGetSymbolAddress((void**)&pA8, g_A8);
    cudaGetSymbolAddress((void**)&pT8, g_T8);
    cudaGetSymbolAddress((void**)&pCnt1, g_cnt1);
    cudaGetSymbolAddress((void**)&pCntd, g_cntd);
    cudaGetSymbolAddress((void**)&pPairs1, g_pairs1);
    cudaGetSymbolAddress((void**)&pPairsd, g_pairsd);
    cudaGetSymbolAddress((void**)&pIdxT, g_idxT);

    // 0: residual add (also zeroes pair counters)
    {
        int n4 = N * 16;
        k_add<<<(n4 + 255) / 256, 256>>>((const float4*)x_feat, (const float4*)f1_ref,
                                         (float4*)pX, n4);
    }
    // 1: conv1 pair lists
    k_build1<<<(N * 27 + 255) / 256, 256>>>(idx1, N * 27);
    // 2: conv1 center (dense GEMM, non-atomic init of F1 with bias)
    k_conv1_center<<<(N + 63) / 64, 256>>>(w1, b1, pX, pF1, N);
    // 3: conv1 offset GEMMs — persistent PIPELINED   <- profiled slot
    k_pair_gemm_p<64, 27, false, true><<<GP_BLOCKS, 128>>>(w1, pPairs1, pCnt1, pX, pF1);
    // 4: downsample pair lists
    k_buildd<<<(N2 * 8 + 255) / 256, 256>>>(idxd, N2 * 8);
    // 5: transpose idx2 for coalesced per-k loads (conv27W)
    k_tidx<<<(N2 + 63) / 64, 256>>>(idx2, pIdxT, N2);

    // down conv (k2/s2): init with bias, persistent NON-pipelined pair GEMM, relu
    k_bias_init32<<<(N2 * 32 + 255) / 256, 256>>>(pF2a, bd, N2 * 32);
    k_pair_gemm_p<32, 8, true, false><<<GP_BLOCKS, 128>>>(wd, pPairsd, pCntd, pF1, pF2a);
    k_relu<<<(N2 * 32 + 255) / 256, 256>>>(pF2a, N2 * 32);

    // --- 3 InceptionResNet blocks (4 launches each) ---
    int gW = (N2 + 63) / 64;            // 2 points/thread -> 64 points/block
    float* F  = pF2a;
    float* Fn = pF2b;
    for (int i = 0; i < 3; i++) {
        const float* W00 = rw00 + (size_t)i * 27 * 32 * 8;
        const float* B00 = rb00 + (size_t)i * 8;
        const float* W01 = rw01 + (size_t)i * 27 * 8 * 16;
        const float* B01 = rb01 + (size_t)i * 16;
        const float* W10 = rw10 + (size_t)i * 32 * 8;
        const float* B10 = rb10 + (size_t)i * 8;
        const float* W11 = rw11 + (size_t)i * 27 * 8 * 8;
        const float* B11 = rb11 + (size_t)i * 8;
        const float* W12 = rw12 + (size_t)i * 8 * 16;
        const float* B12 = rb12 + (size_t)i * 16;

        // A8 = relu(conv27(F, rw00))          [32 -> 8]  warp-split, PB=2
        k_conv27W<true><<<gW, 128>>>(F, pIdxT, W00, B00, pA8, N2);
        // Fn[:, 0:16] = conv27(A8, rw01) + F[:, 0:16]   [8 -> 16]
        k_conv27<8, 16, 2, false, true><<<(N2 + 255) / 256, 128>>>(
            pA8, idx2, W01, B01, F, Fn, 32, 0, N2);
        // T8 = relu(F @ rw10 + b)             [32 -> 8]
        k_pw<32, 8, true, false><<<(N2 + 127) / 128, 128>>>(
            F, W10, B10, nullptr, pT8, 8, 0, N2);
        // Fn[:, 16:32] = relu(conv27(T8, rw11)) @ rw12 + b + F[:, 16:32] [fused epilogue]
        k_conv27_pw8<4><<<(N2 + 511) / 512, 128>>>(
            pT8, idx2, W11, B11, W12, B12, F, Fn, N2);

        float* t = F; F = Fn; Fn = t;
    }

    // --- enc4: conv27(F, w4) + b4 -> output  [32 -> 8]  warp-split, PB=2 ---
    k_conv27W<false><<<gW, 128>>>(F, pIdxT, w4, b4, outp, N2);
}

// round 15
// speedup vs baseline: 1.1569x; 1.1569x over previous
#include <cuda_runtime.h>

// ---------------------------------------------------------------------------
// Static scratch (sanctioned workaround for no-alloc rule)
// ---------------------------------------------------------------------------
#define NMAX 250112  // >= 250000, multiple of 64
#define GP_BLOCKS 912   // 152 SMs x 6 blocks

__device__ __align__(256) float g_X  [(size_t)NMAX * 64];
__device__ __align__(256) float g_F1 [(size_t)NMAX * 64];
__device__ __align__(256) float g_F2a[(size_t)NMAX * 32];
__device__ __align__(256) float g_F2b[(size_t)NMAX * 32];
__device__ __align__(256) float g_A8 [(size_t)NMAX * 8];
__device__ __align__(256) float g_T8 [(size_t)NMAX * 8];
__device__ int  g_cnt1[27];
__device__ int  g_cntd[8];
__device__ __align__(256) int2 g_pairs1[(size_t)27 * NMAX];
__device__ __align__(256) int2 g_pairsd[(size_t)8  * NMAX];
__device__ __align__(256) int  g_idxT [(size_t)27 * NMAX];

typedef unsigned long long u64;

// ---------------------------------------------------------------------------
// Packed f32x2 helpers (SASS FFMA2 — only reachable via PTX fma.rn.f32x2)
// ---------------------------------------------------------------------------
__device__ __forceinline__ u64 pack2(float a, float b) {
    u64 r;
    asm("mov.b64 %0, {%1, %2};" : "=l"(r) : "f"(a), "f"(b));
    return r;
}
__device__ __forceinline__ void unpack2(u64 v, float& a, float& b) {
    asm("mov.b64 {%0, %1}, %2;" : "=f"(a), "=f"(b) : "l"(v));
}
__device__ __forceinline__ u64 fma2(u64 a, u64 b, u64 c) {
    u64 d;
    asm("fma.rn.f32x2 %0, %1, %2, %3;" : "=l"(d) : "l"(a), "l"(b), "l"(c));
    return d;
}
__device__ __forceinline__ u64 add2(u64 a, u64 b) {
    u64 d;
    asm("add.rn.f32x2 %0, %1, %2;" : "=l"(d) : "l"(a), "l"(b));
    return d;
}

// ---------------------------------------------------------------------------
// Vector reduction helper (sm_90+): one LTS request for 4 channels
// ---------------------------------------------------------------------------
__device__ __forceinline__ void red_add_v4(float* p, float4 v) {
    asm volatile("red.global.add.v4.f32 [%0], {%1, %2, %3, %4};"
                 :: "l"(p), "f"(v.x), "f"(v.y), "f"(v.z), "f"(v.w)
                 : "memory");
}

// ---------------------------------------------------------------------------
// Elementwise helpers (k_add also zeroes the pair counters: saves a launch)
// ---------------------------------------------------------------------------
__global__ void k_add(const float4* __restrict__ a, const float4* __restrict__ b,
                      float4* __restrict__ o, int n4) {
    if (blockIdx.x == 0) {
        if (threadIdx.x < 27) g_cnt1[threadIdx.x] = 0;
        if (threadIdx.x >= 32 && threadIdx.x < 40) g_cntd[threadIdx.x - 32] = 0;
    }
    int t = blockIdx.x * blockDim.x + threadIdx.x;
    if (t < n4) {
        float4 x = a[t], y = b[t];
        o[t] = make_float4(x.x + y.x, x.y + y.y, x.z + y.z, x.w + y.w);
    }
}

__global__ void k_bias_init32(float* __restrict__ buf, const float* __restrict__ b, int n) {
    int t = blockIdx.x * blockDim.x + threadIdx.x;
    if (t < n) buf[t] = b[t & 31];
}

__global__ void k_relu(float* __restrict__ buf, int n) {
    int t = blockIdx.x * blockDim.x + threadIdx.x;
    if (t < n) buf[t] = fmaxf(buf[t], 0.0f);
}

// ---------------------------------------------------------------------------
// idx2 transpose: [N,27] -> [27][N] for coalesced per-k index loads.
// ---------------------------------------------------------------------------
__global__ void k_tidx(const int* __restrict__ idx2, int* __restrict__ idxT, int N) {
    __shared__ int tile[64 * 27];
    int base = blockIdx.x * 64;
    int npts = N - base; if (npts > 64) npts = 64;
    int tot = npts * 27;
    for (int e = threadIdx.x; e < tot; e += blockDim.x)
        tile[e] = idx2[(size_t)base * 27 + e];
    __syncthreads();
    for (int e = threadIdx.x; e < 27 * 64; e += blockDim.x) {
        int k = e >> 6, ii = e & 63;
        if (ii < npts) idxT[(size_t)k * N + base + ii] = tile[ii * 27 + k];
    }
}

// ---------------------------------------------------------------------------
// Pair-list construction, VECTORIZED (4 elements/thread, int4 loads) with
// BLOCK-AGGREGATED atomics.
// ---------------------------------------------------------------------------
__global__ void k_build1(const int* __restrict__ idx, int total) {  // total = N*27
    __shared__ int scnt[27];
    __shared__ int sbase[27];
    int tid = threadIdx.x;
    if (tid < 27) scnt[tid] = 0;
    __syncthreads();

    int e0 = (blockIdx.x * blockDim.x + tid) * 4;
    int4 v = make_int4(-1, -1, -1, -1);
    if (e0 + 3 < total) {
        v = *(const int4*)(idx + e0);
    } else {
        if (e0 + 0 < total) v.x = idx[e0 + 0];
        if (e0 + 1 < total) v.y = idx[e0 + 1];
        if (e0 + 2 < total) v.z = idx[e0 + 2];
        if (e0 + 3 < total) v.w = idx[e0 + 3];
    }
    int jj[4] = {v.x, v.y, v.z, v.w};
    int km[4], im[4], rm[4];
#pragma unroll
    for (int m = 0; m < 4; m++) {
        int e = e0 + m;
        int kk = e % 27;
        km[m] = -1;
        if (kk != 13 && jj[m] >= 0) {     // center offset handled densely
            km[m] = kk; im[m] = e / 27;
            rm[m] = atomicAdd(&scnt[kk], 1);
        }
    }
    __syncthreads();
    if (tid < 27 && scnt[tid] > 0)
        sbase[tid] = atomicAdd(&g_cnt1[tid], scnt[tid]);
    __syncthreads();
#pragma unroll
    for (int m = 0; m < 4; m++)
        if (km[m] >= 0)
            g_pairs1[(size_t)km[m] * NMAX + sbase[km[m]] + rm[m]] = make_int2(im[m], jj[m]);
}

__global__ void k_buildd(const int* __restrict__ idx, int total) {  // total = N2*8
    __shared__ int scnt[8];
    __shared__ int sbase[8];
    int tid = threadIdx.x;
    if (tid < 8) scnt[tid] = 0;
    __syncthreads();

    int e0 = (blockIdx.x * blockDim.x + tid) * 4;
    int4 v = make_int4(-1, -1, -1, -1);
    if (e0 + 3 < total) {
        v = *(const int4*)(idx + e0);
    } else {
        if (e0 + 0 < total) v.x = idx[e0 + 0];
        if (e0 + 1 < total) v.y = idx[e0 + 1];
        if (e0 + 2 < total) v.z = idx[e0 + 2];
        if (e0 + 3 < total) v.w = idx[e0 + 3];
    }
    int jj[4] = {v.x, v.y, v.z, v.w};
    int km[4], im[4], rm[4];
#pragma unroll
    for (int m = 0; m < 4; m++) {
        int e = e0 + m;
        km[m] = -1;
        if (jj[m] >= 0) {
            km[m] = e & 7; im[m] = e >> 3;
            rm[m] = atomicAdd(&scnt[km[m]], 1);
        }
    }
    __syncthreads();
    if (tid < 8 && scnt[tid] > 0)
        sbase[tid] = atomicAdd(&g_cntd[tid], scnt[tid]);
    __syncthreads();
#pragma unroll
    for (int m = 0; m < 4; m++)
        if (km[m] >= 0)
            g_pairsd[(size_t)km[m] * NMAX + sbase[km[m]] + rm[m]] = make_int2(im[m], jj[m]);
}

// ---------------------------------------------------------------------------
// conv1 center offset (k==13, identity map): F1 = X @ W13 + b1  (dense GEMM)
// ---------------------------------------------------------------------------
__global__ void k_conv1_center(const float* __restrict__ W, const float* __restrict__ b1,
                               const float* __restrict__ src, float* __restrict__ dst, int N) {
    __shared__ __align__(16) float xs[64][68];
    __shared__ __align__(16) float ws[64][68];
    int tid = threadIdx.x;
    int base = blockIdx.x * 64;

    const float4* W4 = (const float4*)(W + 13 * 4096);
    for (int f = tid; f < 1024; f += 256) {
        int c = f >> 4, oq = f & 15;
        *(float4*)&ws[c][oq * 4] = W4[f];
    }
    int r = tid & 63, cg = tid >> 6;
#pragma unroll
    for (int m = 0; m < 4; m++) {
        int cc = cg * 4 + m;
        float4 v = make_float4(0.f, 0.f, 0.f, 0.f);
        if (base + r < N) v = ((const float4*)src)[(size_t)(base + r) * 16 + cc];
        xs[cc * 4 + 0][r] = v.x; xs[cc * 4 + 1][r] = v.y;
        xs[cc * 4 + 2][r] = v.z; xs[cc * 4 + 3][r] = v.w;
    }
    __syncthreads();

    int p0 = (tid & 15) * 4, o0 = (tid >> 4) * 4;
    u64 acc2[4][2] = {};
#pragma unroll 8
    for (int c = 0; c < 64; c++) {
        float4 a = *(float4*)&xs[c][p0];
        u64 w01 = *(const u64*)&ws[c][o0];
        u64 w23 = *(const u64*)&ws[c][o0 + 2];
        float ap[4] = {a.x, a.y, a.z, a.w};
#pragma unroll
        for (int p = 0; p < 4; p++) {
            u64 ad = pack2(ap[p], ap[p]);
            acc2[p][0] = fma2(ad, w01, acc2[p][0]);
            acc2[p][1] = fma2(ad, w23, acc2[p][1]);
        }
    }
    float4 bb = ((const float4*)b1)[o0 >> 2];
#pragma unroll
    for (int p = 0; p < 4; p++) {
        int i = base + p0 + p;
        if (i < N) {
            float a0, a1, a2, a3;
            unpack2(acc2[p][0], a0, a1);
            unpack2(acc2[p][1], a2, a3);
            float4 o = make_float4(a0 + bb.x, a1 + bb.y, a2 + bb.z, a3 + bb.w);
            ((float4*)dst)[(size_t)i * 16 + (o0 >> 2)] = o;
        }
    }
}

// ---------------------------------------------------------------------------
// PERSISTENT pair-compacted gather-GEMM. PIPE selects register-prefetch
// software pipelining (good for COUT=64's long compute body; bad for COUT=32).
// ---------------------------------------------------------------------------
template <int COUT, int NK, bool RELU_SRC, bool PIPE>
__global__ void __launch_bounds__(128, 4)
k_pair_gemm_p(const float* __restrict__ W, const int2* __restrict__ pairsBase,
              const int* __restrict__ cntArr,
              const float* __restrict__ src, float* __restrict__ dst) {
    constexpr int CT = COUT / 8;          // couts per thread: 64->8, 32->4
    __shared__ __align__(16) float xs[64][68];
    __shared__ __align__(16) float ws[64][COUT + 4];
    __shared__ int sdst[64];
    __shared__ int ssrc[64];
    __shared__ int spre[NK + 1];
    __shared__ int scnt[NK];

    int tid = threadIdx.x;
    if (tid < NK) scnt[tid] = cntArr[tid];
    __syncthreads();
    if (tid == 0) {
        int s = 0;
        for (int k = 0; k < NK; k++) { spre[k] = s; s += (scnt[k] + 63) >> 6; }
        spre[NK] = s;
    }
    __syncthreads();

    int total = spre[NK];
    int chunk = (total + gridDim.x - 1) / gridDim.x;
    int tile  = blockIdx.x * chunk;
    int tEnd  = min(tile + chunk, total);
    if (tile >= tEnd) return;

    int pg = tid & 15, og = tid >> 4;     // 16 pair-groups x 8 chan-groups
    int p0 = pg * 4, o0 = og * CT;
    int row0 = tid >> 2, cl = tid & 3;    // gather rows row0, row0+32

    int kcur = 0;
    while (spre[kcur + 1] <= tile) kcur++;
    int kprev = -1;

    if (PIPE) {
        float4 v0[4], v1[4];
        int dpre;
        {
            int t0 = (tile - spre[kcur]) * 64;
            int n  = scnt[kcur];
            const int2* pb = pairsBase + (size_t)kcur * NMAX + t0;
            int j0 = (t0 + row0      < n) ? pb[row0].y      : -1;
            int j1 = (t0 + row0 + 32 < n) ? pb[row0 + 32].y : -1;
            dpre = (tid < 64 && t0 + tid < n) ? pb[tid].x : -1;
            const float4* s0 = (j0 >= 0) ? ((const float4*)src) + (size_t)j0 * 16 : nullptr;
            const float4* s1 = (j1 >= 0) ? ((const float4*)src) + (size_t)j1 * 16 : nullptr;
#pragma unroll
            for (int m = 0; m < 4; m++) {
                int col = cl + m * 4;
                float4 a = make_float4(0.f, 0.f, 0.f, 0.f), bb = a;
                if (s0) a  = s0[col];
                if (s1) bb = s1[col];
                v0[m] = a; v1[m] = bb;
            }
        }

        for (;;) {
            __syncthreads();
            if (kcur != kprev) {
                const float4* W4 = (const float4*)(W + (size_t)kcur * 64 * COUT);
                for (int f = tid; f < 64 * COUT / 4; f += 128) {
                    int c = f / (COUT / 4), oq = f % (COUT / 4);
                    *(float4*)&ws[c][oq * 4] = W4[f];
                }
                kprev = kcur;
            }
#pragma unroll
            for (int m = 0; m < 4; m++) {
                int c = (cl + m * 4) * 4;
                xs[c + 0][row0] = v0[m].x; xs[c + 1][row0] = v0[m].y;
                xs[c + 2][row0] = v0[m].z; xs[c + 3][row0] = v0[m].w;
                xs[c + 0][row0 + 32] = v1[m].x; xs[c + 1][row0 + 32] = v1[m].y;
                xs[c + 2][row0 + 32] = v1[m].z; xs[c + 3][row0 + 32] = v1[m].w;
            }
            if (tid < 64) sdst[tid] = dpre;
            __syncthreads();

            int tnext = tile + 1;
            bool more = (tnext < tEnd);
            int knext = kcur;
            if (more) {
                while (spre[knext + 1] <= tnext) knext++;
                int t0 = (tnext - spre[knext]) * 64;
                int n  = scnt[knext];
                const int2* pb = pairsBase + (size_t)knext * NMAX + t0;
                int j0 = (t0 + row0      < n) ? pb[row0].y      : -1;
                int j1 = (t0 + row0 + 32 < n) ? pb[row0 + 32].y : -1;
                dpre = (tid < 64 && t0 + tid < n) ? pb[tid].x : -1;
                const float4* s0 = (j0 >= 0) ? ((const float4*)src) + (size_t)j0 * 16 : nullptr;
                const float4* s1 = (j1 >= 0) ? ((const float4*)src) + (size_t)j1 * 16 : nullptr;
#pragma unroll
                for (int m = 0; m < 4; m++) {
                    int col = cl + m * 4;
                    float4 a = make_float4(0.f, 0.f, 0.f, 0.f), bb = a;
                    if (s0) a  = s0[col];
                    if (s1) bb = s1[col];
                    v0[m] = a; v1[m] = bb;
                }
            }

            u64 acc2[4][CT / 2] = {};
#pragma unroll 8
            for (int c = 0; c < 64; c++) {
                u64 wq[CT / 2];
                if (CT == 8) {
                    ulonglong2 wA = *(const ulonglong2*)&ws[c][o0];
                    ulonglong2 wB = *(const ulonglong2*)&ws[c][o0 + 4];
                    wq[0] = wA.x; wq[1] = wA.y; wq[2] = wB.x; wq[3] = wB.y;
                } else {
                    ulonglong2 wA = *(const ulonglong2*)&ws[c][o0];
                    wq[0] = wA.x; wq[1] = wA.y;
                }
                float4 a4 = *(float4*)&xs[c][p0];
                float a[4] = {a4.x, a4.y, a4.z, a4.w};
#pragma unroll
                for (int p = 0; p < 4; p++) {
                    u64 ad = pack2(a[p], a[p]);
#pragma unroll
                    for (int q = 0; q < CT / 2; q++)
                        acc2[p][q] = fma2(ad, wq[q], acc2[p][q]);
                }
            }
#pragma unroll
            for (int p = 0; p < 4; p++) {
                int d = sdst[p0 + p];
                if (d >= 0) {
#pragma unroll
                    for (int h = 0; h < CT / 4; h++) {
                        float4 v;
                        unpack2(acc2[p][h * 2 + 0], v.x, v.y);
                        unpack2(acc2[p][h * 2 + 1], v.z, v.w);
                        red_add_v4(&dst[(size_t)d * COUT + o0 + h * 4], v);
                    }
                }
            }

            if (!more) break;
            tile = tnext; kcur = knext;
        }
    } else {
        for (; tile < tEnd; ++tile) {
            while (spre[kcur + 1] <= tile) kcur++;

            __syncthreads();
            if (kcur != kprev) {
                const float4* W4 = (const float4*)(W + (size_t)kcur * 64 * COUT);
                for (int f = tid; f < 64 * COUT / 4; f += 128) {
                    int c = f / (COUT / 4), oq = f % (COUT / 4);
                    *(float4*)&ws[c][oq * 4] = W4[f];
                }
                kprev = kcur;
            }
            int t0 = (tile - spre[kcur]) * 64;
            int n  = scnt[kcur];
            if (tid < 64) {
                int2 pr = make_int2(-1, -1);
                if (t0 + tid < n) pr = pairsBase[(size_t)kcur * NMAX + t0 + tid];
                sdst[tid] = pr.x; ssrc[tid] = pr.y;
            }
            __syncthreads();

#pragma unroll
            for (int pass = 0; pass < 2; pass++) {
                int row = row0 + pass * 32;
                int j = ssrc[row];
                const float4* srow = (j >= 0) ? ((const float4*)src) + (size_t)j * 16 : nullptr;
#pragma unroll
                for (int m = 0; m < 4; m++) {
                    int col = cl + m * 4;
                    float4 v = make_float4(0.f, 0.f, 0.f, 0.f);
                    if (srow) v = srow[col];
                    if (RELU_SRC) {
                        v.x = fmaxf(v.x, 0.f); v.y = fmaxf(v.y, 0.f);
                        v.z = fmaxf(v.z, 0.f); v.w = fmaxf(v.w, 0.f);
                    }
                    int c = col * 4;
                    xs[c + 0][row] = v.x; xs[c + 1][row] = v.y;
                    xs[c + 2][row] = v.z; xs[c + 3][row] = v.w;
                }
            }
            __syncthreads();

            u64 acc2[4][CT / 2] = {};
#pragma unroll 8
            for (int c = 0; c < 64; c++) {
                u64 wq[CT / 2];
                if (CT == 8) {
                    ulonglong2 wA = *(const ulonglong2*)&ws[c][o0];
                    ulonglong2 wB = *(const ulonglong2*)&ws[c][o0 + 4];
                    wq[0] = wA.x; wq[1] = wA.y; wq[2] = wB.x; wq[3] = wB.y;
                } else {
                    ulonglong2 wA = *(const ulonglong2*)&ws[c][o0];
                    wq[0] = wA.x; wq[1] = wA.y;
                }
                float4 a4 = *(float4*)&xs[c][p0];
                float a[4] = {a4.x, a4.y, a4.z, a4.w};
#pragma unroll
                for (int p = 0; p < 4; p++) {
                    u64 ad = pack2(a[p], a[p]);
#pragma unroll
                    for (int q = 0; q < CT / 2; q++)
                        acc2[p][q] = fma2(ad, wq[q], acc2[p][q]);
                }
            }
#pragma unroll
            for (int p = 0; p < 4; p++) {
                int d = sdst[p0 + p];
                if (d >= 0) {
#pragma unroll
                    for (int h = 0; h < CT / 4; h++) {
                        float4 v;
                        unpack2(acc2[p][h * 2 + 0], v.x, v.y);
                        unpack2(acc2[p][h * 2 + 1], v.z, v.w);
                        red_add_v4(&dst[(size_t)d * COUT + o0 + h * 4], v);
                    }
                }
            }
        }
    }
}

// ---------------------------------------------------------------------------
// Warp-split 27-offset conv, CIN=32 -> COUT=8 (round-12 proven form, PB=4).
// FROZEN: rounds 4/11/13 all failed to improve this kernel's structure.
// ---------------------------------------------------------------------------
template <bool RELU>
__global__ void __launch_bounds__(128)
k_conv27W(const float* __restrict__ feat, const int* __restrict__ idxT,
          const float* __restrict__ W, const float* __restrict__ b,
          float* __restrict__ out, int N) {
    __shared__ __align__(16) u64 wsm[27 * 8 * 4 * 4];  // 3456 u64 = 27.6 KB
    __shared__ float sbv[8];
    int tid = threadIdx.x;

    for (int f = tid; f < 3456; f += 128) {
        int k = f >> 7, r = f & 127;
        int cc = r >> 4, q = (r >> 2) & 3, op = r & 3;
        float2 w2 = *(const float2*)&W[k * 256 + (q * 8 + cc) * 8 + op * 2];
        wsm[f] = pack2(w2.x, w2.y);
    }
    if (tid < 8) sbv[tid] = b[tid];
    __syncthreads();

    int q = tid & 3, pb = tid >> 2;
    int i0 = blockIdx.x * 128 + pb;      // points i0, i0+32, i0+64, i0+96

    u64 acc[4][4] = {};

    for (int k = 0; k < 27; k++) {
        const int* ik = idxT + (size_t)k * N;
        int j[4];
#pragma unroll
        for (int p = 0; p < 4; p++) {
            int i = i0 + p * 32;
            j[p] = (i < N) ? ik[i] : -1;
        }
        bool any = (j[0] >= 0) | (j[1] >= 0) | (j[2] >= 0) | (j[3] >= 0);
        if (__ballot_sync(0xFFFFFFFFu, any) == 0) continue;

        float fr[4][8];
#pragma unroll
        for (int p = 0; p < 4; p++) {
            float4 A = make_float4(0.f, 0.f, 0.f, 0.f), B = A;
            if (j[p] >= 0) {
                const float4* fp = (const float4*)(feat + (size_t)j[p] * 32 + q * 8);
                A = fp[0]; B = fp[1];
            }
            fr[p][0] = A.x; fr[p][1] = A.y; fr[p][2] = A.z; fr[p][3] = A.w;
            fr[p][4] = B.x; fr[p][5] = B.y; fr[p][6] = B.z; fr[p][7] = B.w;
        }

        const u64* wkq = wsm + k * 128 + q * 4;
#pragma unroll
        for (int cc = 0; cc < 8; cc++) {
            const ulonglong2* wp = (const ulonglong2*)(wkq + cc * 16);
            ulonglong2 wA = wp[0];          // out pairs (0,1),(2,3)
            ulonglong2 wB = wp[1];          // out pairs (4,5),(6,7)
#pragma unroll
            for (int p = 0; p < 4; p++) {
                u64 ad = pack2(fr[p][cc], fr[p][cc]);
                acc[p][0] = fma2(ad, wA.x, acc[p][0]);
                acc[p][1] = fma2(ad, wA.y, acc[p][1]);
                acc[p][2] = fma2(ad, wB.x, acc[p][2]);
                acc[p][3] = fma2(ad, wB.y, acc[p][3]);
            }
        }
    }

    // reduce across the 4 q-lanes of each point (consecutive lanes)
#pragma unroll
    for (int p = 0; p < 4; p++) {
#pragma unroll
        for (int m = 0; m < 4; m++) {
            u64 o1 = __shfl_down_sync(0xFFFFFFFFu, acc[p][m], 1, 4);
            acc[p][m] = add2(acc[p][m], o1);
            u64 o2 = __shfl_down_sync(0xFFFFFFFFu, acc[p][m], 2, 4);
            acc[p][m] = add2(acc[p][m], o2);
        }
    }

    if (q == 0) {
#pragma unroll
        for (int p = 0; p < 4; p++) {
            int i = i0 + p * 32;
            if (i < N) {
                float t[8];
                unpack2(acc[p][0], t[0], t[1]);
                unpack2(acc[p][1], t[2], t[3]);
                unpack2(acc[p][2], t[4], t[5]);
                unpack2(acc[p][3], t[6], t[7]);
#pragma unroll
                for (int o = 0; o < 8; o++) {
                    float x = t[o] + sbv[o];
                    if (RELU) x = fmaxf(x, 0.0f);
                    t[o] = x;
                }
                float* op = out + (size_t)i * 8;
                ((float4*)op)[0] = make_float4(t[0], t[1], t[2], t[3]);
                ((float4*)op)[1] = make_float4(t[4], t[5], t[6], t[7]);
            }
        }
    }
}

// ---------------------------------------------------------------------------
// Dense-k 27-offset conv, small CIN (=8) — round-3 proven per-point form.
// ---------------------------------------------------------------------------
template <int CIN, int COUT, int PT, bool RELU, bool RES>
__global__ void k_conv27(const float* __restrict__ feat, const int* __restrict__ idx,
                         const float* __restrict__ W, const float* __restrict__ b,
                         const float* __restrict__ res, float* __restrict__ out,
                         int outStride, int outOff, int N) {
    __shared__ __align__(16) float ws[27 * CIN * COUT];
    __shared__ float sb[COUT];
    int tid = threadIdx.x;
    for (int f = tid; f < 27 * CIN * COUT; f += blockDim.x) ws[f] = W[f];
    if (tid < COUT) sb[tid] = b[tid];
    __syncthreads();

    int i0 = (blockIdx.x * blockDim.x + tid) * PT;

    u64 acc[PT][COUT / 2] = {};

    for (int k = 0; k < 27; k++) {
        int jj[PT];
#pragma unroll
        for (int p = 0; p < PT; p++) {
            int i = i0 + p;
            jj[p] = (i < N) ? idx[(size_t)i * 27 + k] : -1;
        }
        const float* wk = &ws[k * CIN * COUT];
#pragma unroll
        for (int c4 = 0; c4 < CIN / 4; c4++) {
            float vv[PT][4];
#pragma unroll
            for (int p = 0; p < PT; p++) {
                float4 v = make_float4(0.f, 0.f, 0.f, 0.f);
                if (jj[p] >= 0) v = ((const float4*)feat)[(size_t)jj[p] * (CIN / 4) + c4];
                vv[p][0] = v.x; vv[p][1] = v.y; vv[p][2] = v.z; vv[p][3] = v.w;
            }
#pragma unroll
            for (int cc = 0; cc < 4; cc++) {
                const u64* w2 = (const u64*)&wk[(c4 * 4 + cc) * COUT];
                u64 wq[COUT / 2];
#pragma unroll
                for (int qq = 0; qq < COUT / 2; qq++) wq[qq] = w2[qq];
#pragma unroll
                for (int p = 0; p < PT; p++) {
                    u64 ad = pack2(vv[p][cc], vv[p][cc]);
#pragma unroll
                    for (int qq = 0; qq < COUT / 2; qq++)
                        acc[p][qq] = fma2(ad, wq[qq], acc[p][qq]);
                }
            }
        }
    }

#pragma unroll
    for (int p = 0; p < PT; p++) {
        int i = i0 + p;
        if (i < N) {
            float tmp[COUT];
#pragma unroll
            for (int qq = 0; qq < COUT / 2; qq++)
                unpack2(acc[p][qq], tmp[2 * qq], tmp[2 * qq + 1]);
#pragma unroll
            for (int o = 0; o < COUT; o++) {
                float x = tmp[o] + sb[o];
                if (RELU) x = fmaxf(x, 0.0f);
                tmp[o] = x;
            }
            float* op = out + (size_t)i * outStride + outOff;
            const float* rp = RES ? (res + (size_t)i * 32 + outOff) : nullptr;
#pragma unroll
            for (int qq = 0; qq < COUT / 4; qq++) {
                float4 t4 = make_float4(tmp[qq * 4 + 0], tmp[qq * 4 + 1],
                                        tmp[qq * 4 + 2], tmp[qq * 4 + 3]);
                if (RES) {
                    float4 r4 = ((const float4*)rp)[qq];
                    t4.x += r4.x; t4.y += r4.y; t4.z += r4.z; t4.w += r4.w;
                }
                ((float4*)op)[qq] = t4;
            }
        }
    }
}

// ---------------------------------------------------------------------------
// FUSED conv27 (8->8, relu) + pointwise (8->16) + bias + residual (EPILOGUE
// fusion only — loop body identical to proven k_conv27<8,8,PT>):
//   Fn[i, 16:32] = relu(conv27(T8, W11)+B11) @ W12 + B12 + F[i, 16:32]
// ---------------------------------------------------------------------------
template <int PT>
__global__ void k_conv27_pw8(const float* __restrict__ feat, const int* __restrict__ idx,
                             const float* __restrict__ W, const float* __restrict__ b,
                             const float* __restrict__ W12, const float* __restrict__ b12,
                             const float* __restrict__ res, float* __restrict__ out, int N) {
    __shared__ __align__(16) float ws[27 * 64];      // 27x8x8 conv weights
    __shared__ __align__(16) u64 w12p[64];           // 8x16 pw weights, paired
    __shared__ float sb[8];
    __shared__ float sb12[16];
    int tid = threadIdx.x;
    for (int f = tid; f < 27 * 64; f += blockDim.x) ws[f] = W[f];
    if (tid < 64) {
        int c = tid >> 3, op = tid & 7;
        float2 w2 = *(const float2*)&W12[c * 16 + op * 2];
        w12p[tid] = pack2(w2.x, w2.y);
    }
    if (tid < 8)  sb[tid] = b[tid];
    if (tid < 16) sb12[tid] = b12[tid];
    __syncthreads();

    int i0 = (blockIdx.x * blockDim.x + tid) * PT;

    u64 acc[PT][4] = {};

    for (int k = 0; k < 27; k++) {
        int jj[PT];
#pragma unroll
        for (int p = 0; p < PT; p++) {
            int i = i0 + p;
            jj[p] = (i < N) ? idx[(size_t)i * 27 + k] : -1;
        }
        const float* wk = &ws[k * 64];
#pragma unroll
        for (int c4 = 0; c4 < 2; c4++) {
            float vv[PT][4];
#pragma unroll
            for (int p = 0; p < PT; p++) {
                float4 v = make_float4(0.f, 0.f, 0.f, 0.f);
                if (jj[p] >= 0) v = ((const float4*)feat)[(size_t)jj[p] * 2 + c4];
                vv[p][0] = v.x; vv[p][1] = v.y; vv[p][2] = v.z; vv[p][3] = v.w;
            }
#pragma unroll
            for (int cc = 0; cc < 4; cc++) {
                const u64* w2 = (const u64*)&wk[(c4 * 4 + cc) * 8];
                u64 wq[4];
#pragma unroll
                for (int qq = 0; qq < 4; qq++) wq[qq] = w2[qq];
#pragma unroll
                for (int p = 0; p < PT; p++) {
                    u64 ad = pack2(vv[p][cc], vv[p][cc]);
#pragma unroll
                    for (int qq = 0; qq < 4; qq++)
                        acc[p][qq] = fma2(ad, wq[qq], acc[p][qq]);
                }
            }
        }
    }

#pragma unroll
    for (int p = 0; p < PT; p++) {
        int i = i0 + p;
        if (i < N) {
            float tmp[8];
#pragma unroll
            for (int qq = 0; qq < 4; qq++)
                unpack2(acc[p][qq], tmp[2 * qq], tmp[2 * qq + 1]);
#pragma unroll
            for (int o = 0; o < 8; o++)
                tmp[o] = fmaxf(tmp[o] + sb[o], 0.0f);

            // pointwise 8->16 (epilogue registers only)
            u64 opw[8] = {};
#pragma unroll
            for (int cc = 0; cc < 8; cc++) {
                u64 ad = pack2(tmp[cc], tmp[cc]);
                const u64* wrow = w12p + cc * 8;
#pragma unroll
                for (int jq = 0; jq < 8; jq++)
                    opw[jq] = fma2(ad, wrow[jq], opw[jq]);
            }
            float o16[16];
#pragma unroll
            for (int jq = 0; jq < 8; jq++)
                unpack2(opw[jq], o16[2 * jq], o16[2 * jq + 1]);

            float* op = out + (size_t)i * 32 + 16;
            const float* rp = res + (size_t)i * 32 + 16;
#pragma unroll
            for (int qq = 0; qq < 4; qq++) {
                float4 r4 = ((const float4*)rp)[qq];
                float4 t4 = make_float4(o16[qq * 4 + 0] + sb12[qq * 4 + 0] + r4.x,
                                        o16[qq * 4 + 1] + sb12[qq * 4 + 1] + r4.y,
                                        o16[qq * 4 + 2] + sb12[qq * 4 + 2] + r4.z,
                                        o16[qq * 4 + 3] + sb12[qq * 4 + 3] + r4.w);
                ((float4*)op)[qq] = t4;
            }
        }
    }
}

// ---------------------------------------------------------------------------
// Pointwise (kernel-size-1) conv: out = (relu?)(feat @ W + b) (+ res)
// ---------------------------------------------------------------------------
template <int CIN, int COUT, bool RELU, bool RES>
__global__ void k_pw(const float* __restrict__ feat, const float* __restrict__ W,
                     const float* __restrict__ b, const float* __restrict__ res,
                     float* __restrict__ out, int outStride, int outOff, int N) {
    __shared__ __align__(16) float ws[CIN * COUT];
    __shared__ float sb[COUT];
    int tid = threadIdx.x;
    for (int f = tid; f < CIN * COUT; f += blockDim.x) ws[f] = W[f];
    if (tid < COUT) sb[tid] = b[tid];
    __syncthreads();

    int i = blockIdx.x * blockDim.x + tid;
    if (i >= N) return;

    u64 acc[COUT / 2] = {};

#pragma unroll
    for (int c4 = 0; c4 < CIN / 4; c4++) {
        float4 v = ((const float4*)feat)[(size_t)i * (CIN / 4) + c4];
        float vv[4] = {v.x, v.y, v.z, v.w};
#pragma unroll
        for (int cc = 0; cc < 4; cc++) {
            const u64* w2 = (const u64*)&ws[(c4 * 4 + cc) * COUT];
            u64 ad = pack2(vv[cc], vv[cc]);
#pragma unroll
            for (int qq = 0; qq < COUT / 2; qq++)
                acc[qq] = fma2(ad, w2[qq], acc[qq]);
        }
    }

    float tmp[COUT];
#pragma unroll
    for (int qq = 0; qq < COUT / 2; qq++)
        unpack2(acc[qq], tmp[2 * qq], tmp[2 * qq + 1]);

    float* op = out + (size_t)i * outStride + outOff;
#pragma unroll
    for (int qq = 0; qq < COUT / 4; qq++) {
        float4 t4 = make_float4(tmp[qq * 4 + 0] + sb[qq * 4 + 0], tmp[qq * 4 + 1] + sb[qq * 4 + 1],
                                tmp[qq * 4 + 2] + sb[qq * 4 + 2], tmp[qq * 4 + 3] + sb[qq * 4 + 3]);
        if (RELU) {
            t4.x = fmaxf(t4.x, 0.f); t4.y = fmaxf(t4.y, 0.f);
            t4.z = fmaxf(t4.z, 0.f); t4.w = fmaxf(t4.w, 0.f);
        }
        if (RES) {
            float4 r4 = ((const float4*)(res + (size_t)i * 32 + outOff))[qq];
            t4.x += r4.x; t4.y += r4.y; t4.z += r4.z; t4.w += r4.w;
        }
        ((float4*)op)[qq] = t4;
    }
}

// ---------------------------------------------------------------------------
// Host launcher
// ---------------------------------------------------------------------------
extern "C" void kernel_launch(void* const* d_in, const int* in_sizes, int n_in,
                              void* d_out, int out_size) {
    const float* x_feat = (const float*)d_in[0];
    const float* f1_ref = (const float*)d_in[1];
    const float* w1     = (const float*)d_in[2];
    const float* b1     = (const float*)d_in[3];
    const float* wd     = (const float*)d_in[4];
    const float* bd     = (const float*)d_in[5];
    const float* rw00   = (const float*)d_in[6];
    const float* rb00   = (const float*)d_in[7];
    const float* rw01   = (const float*)d_in[8];
    const float* rb01   = (const float*)d_in[9];
    const float* rw10   = (const float*)d_in[10];
    const float* rb10   = (const float*)d_in[11];
    const float* rw11   = (const float*)d_in[12];
    const float* rb11   = (const float*)d_in[13];
    const float* rw12   = (const float*)d_in[14];
    const float* rb12   = (const float*)d_in[15];
    const float* w4     = (const float*)d_in[16];
    const float* b4     = (const float*)d_in[17];
    const int*   idx1   = (const int*)d_in[18];
    const int*   idxd   = (const int*)d_in[19];
    const int*   idx2   = (const int*)d_in[20];
    float* outp = (float*)d_out;

    int N  = in_sizes[0] / 64;
    int N2 = in_sizes[19] / 8;

    float *pX, *pF1, *pF2a, *pF2b, *pA8, *pT8;
    int *pCnt1, *pCntd, *pIdxT;
    int2 *pPairs1, *pPairsd;
    cudaGetSymbolAddress((void**)&pX, g_X);
    cudaGetSymbolAddress((void**)&pF1, g_F1);
    cudaGetSymbolAddress((void**)&pF2a, g_F2a);
    cudaGetSymbolAddress((void**)&pF2b, g_F2b);
    cudaGetSymbolAddress((void**)&pA8, g_A8);
    cudaGetSymbolAddress((void**)&pT8, g_T8);
    cudaGetSymbolAddress((void**)&pCnt1, g_cnt1);
    cudaGetSymbolAddress((void**)&pCntd, g_cntd);
    cudaGetSymbolAddress((void**)&pPairs1, g_pairs1);
    cudaGetSymbolAddress((void**)&pPairsd, g_pairsd);
    cudaGetSymbolAddress((void**)&pIdxT, g_idxT);

    // 0: residual add (also zeroes pair counters)
    {
        int n4 = N * 16;
        k_add<<<(n4 + 255) / 256, 256>>>((const float4*)x_feat, (const float4*)f1_ref,
                                         (float4*)pX, n4);
    }
    // 1: conv1 pair lists (vectorized, 4 elem/thread)
    {
        int total = N * 27;
        int thr = (total + 3) / 4;
        k_build1<<<(thr + 255) / 256, 256>>>(idx1, total);
    }
    // 2: conv1 center (dense GEMM, non-atomic init of F1 with bias)
    k_conv1_center<<<(N + 63) / 64, 256>>>(w1, b1, pX, pF1, N);
    // 3: conv1 offset GEMMs — persistent PIPELINED   <- profiled slot
    k_pair_gemm_p<64, 27, false, true><<<GP_BLOCKS, 128>>>(w1, pPairs1, pCnt1, pX, pF1);
    // 4: downsample pair lists (vectorized)
    {
        int total = N2 * 8;
        int thr = (total + 3) / 4;
        k_buildd<<<(thr + 255) / 256, 256>>>(idxd, total);
    }
    // 5: transpose idx2 for coalesced per-k loads (conv27W)
    k_tidx<<<(N2 + 63) / 64, 256>>>(idx2, pIdxT, N2);

    // down conv (k2/s2): init with bias, persistent NON-pipelined pair GEMM, relu
    k_bias_init32<<<(N2 * 32 + 255) / 256, 256>>>(pF2a, bd, N2 * 32);
    k_pair_gemm_p<32, 8, true, false><<<GP_BLOCKS, 128>>>(wd, pPairsd, pCntd, pF1, pF2a);
    k_relu<<<(N2 * 32 + 255) / 256, 256>>>(pF2a, N2 * 32);

    // --- 3 InceptionResNet blocks (4 launches each) ---
    int gW = (N2 + 127) / 128;          // PB=4: 128 points/block (round-12 form)
    float* F  = pF2a;
    float* Fn = pF2b;
    for (int i = 0; i < 3; i++) {
        const float* W00 = rw00 + (size_t)i * 27 * 32 * 8;
        const float* B00 = rb00 + (size_t)i * 8;
        const float* W01 = rw01 + (size_t)i * 27 * 8 * 16;
        const float* B01 = rb01 + (size_t)i * 16;
        const float* W10 = rw10 + (size_t)i * 32 * 8;
        const float* B10 = rb10 + (size_t)i * 8;
        const float* W11 = rw11 + (size_t)i * 27 * 8 * 8;
        const float* B11 = rb11 + (size_t)i * 8;
        const float* W12 = rw12 + (size_t)i * 8 * 16;
        const float* B12 = rb12 + (size_t)i * 16;

        // A8 = relu(conv27(F, rw00))          [32 -> 8]  warp-split, PB=4
        k_conv27W<true><<<gW, 128>>>(F, pIdxT, W00, B00, pA8, N2);
        // Fn[:, 0:16] = conv27(A8, rw01) + F[:, 0:16]   [8 -> 16]
        k_conv27<8, 16, 2, false, true><<<(N2 + 255) / 256, 128>>>(
            pA8, idx2, W01, B01, F, Fn, 32, 0, N2);
        // T8 = relu(F @ rw10 + b)             [32 -> 8]
        k_pw<32, 8, true, false><<<(N2 + 127) / 128, 128>>>(
            F, W10, B10, nullptr, pT8, 8, 0, N2);
        // Fn[:, 16:32] = relu(conv27(T8, rw11)) @ rw12 + b + F[:, 16:32] [fused epilogue]
        k_conv27_pw8<4><<<(N2 + 511) / 512, 128>>>(
            pT8, idx2, W11, B11, W12, B12, F, Fn, N2);

        float* t = F; F = Fn; Fn = t;
    }

    // --- enc4: conv27(F, w4) + b4 -> output  [32 -> 8]  warp-split, PB=4 ---
    k_conv27W<false><<<gW, 128>>>(F, pIdxT, w4, b4, outp, N2);
}

// round 16
// speedup vs baseline: 1.2155x; 1.0506x over previous
#include <cuda_runtime.h>

// ---------------------------------------------------------------------------
// Static scratch (sanctioned workaround for no-alloc rule)
// ---------------------------------------------------------------------------
#define NMAX 250112  // >= 250000, multiple of 64
#define GP_BLOCKS 912   // 152 SMs x 6 blocks

__device__ __align__(256) float g_X  [(size_t)NMAX * 64];
__device__ __align__(256) float g_F1 [(size_t)NMAX * 64];
__device__ __align__(256) float g_F2a[(size_t)NMAX * 32];
__device__ __align__(256) float g_F2b[(size_t)NMAX * 32];
__device__ __align__(256) float g_A8 [(size_t)NMAX * 8];
__device__ __align__(256) float g_T8 [(size_t)NMAX * 8];
__device__ int  g_cnt1[27];
__device__ int  g_cntd[8];
__device__ __align__(256) int2 g_pairs1[(size_t)27 * NMAX];
__device__ __align__(256) int2 g_pairsd[(size_t)8  * NMAX];
__device__ __align__(256) int  g_idxT [(size_t)27 * NMAX];

typedef unsigned long long u64;

// ---------------------------------------------------------------------------
// Packed f32x2 helpers (SASS FFMA2 — only reachable via PTX fma.rn.f32x2)
// ---------------------------------------------------------------------------
__device__ __forceinline__ u64 pack2(float a, float b) {
    u64 r;
    asm("mov.b64 %0, {%1, %2};" : "=l"(r) : "f"(a), "f"(b));
    return r;
}
__device__ __forceinline__ void unpack2(u64 v, float& a, float& b) {
    asm("mov.b64 {%0, %1}, %2;" : "=f"(a), "=f"(b) : "l"(v));
}
__device__ __forceinline__ u64 fma2(u64 a, u64 b, u64 c) {
    u64 d;
    asm("fma.rn.f32x2 %0, %1, %2, %3;" : "=l"(d) : "l"(a), "l"(b), "l"(c));
    return d;
}
__device__ __forceinline__ u64 add2(u64 a, u64 b) {
    u64 d;
    asm("add.rn.f32x2 %0, %1, %2;" : "=l"(d) : "l"(a), "l"(b));
    return d;
}

// ---------------------------------------------------------------------------
// Vector reduction helper (sm_90+): one LTS request for 4 channels
// ---------------------------------------------------------------------------
__device__ __forceinline__ void red_add_v4(float* p, float4 v) {
    asm volatile("red.global.add.v4.f32 [%0], {%1, %2, %3, %4};"
                 :: "l"(p), "f"(v.x), "f"(v.y), "f"(v.z), "f"(v.w)
                 : "memory");
}

// ---------------------------------------------------------------------------
// Elementwise helpers (k_add also zeroes the pair counters: saves a launch)
// ---------------------------------------------------------------------------
__global__ void k_add(const float4* __restrict__ a, const float4* __restrict__ b,
                      float4* __restrict__ o, int n4) {
    if (blockIdx.x == 0) {
        if (threadIdx.x < 27) g_cnt1[threadIdx.x] = 0;
        if (threadIdx.x >= 32 && threadIdx.x < 40) g_cntd[threadIdx.x - 32] = 0;
    }
    int t = blockIdx.x * blockDim.x + threadIdx.x;
    if (t < n4) {
        float4 x = a[t], y = b[t];
        o[t] = make_float4(x.x + y.x, x.y + y.y, x.z + y.z, x.w + y.w);
    }
}

__global__ void k_bias_init32(float* __restrict__ buf, const float* __restrict__ b, int n) {
    int t = blockIdx.x * blockDim.x + threadIdx.x;
    if (t < n) buf[t] = b[t & 31];
}

__global__ void k_relu(float* __restrict__ buf, int n) {
    int t = blockIdx.x * blockDim.x + threadIdx.x;
    if (t < n) buf[t] = fmaxf(buf[t], 0.0f);
}

// ---------------------------------------------------------------------------
// idx2 transpose: [N,27] -> [27][N] for coalesced per-k index loads.
// ---------------------------------------------------------------------------
__global__ void k_tidx(const int* __restrict__ idx2, int* __restrict__ idxT, int N) {
    __shared__ int tile[64 * 27];
    int base = blockIdx.x * 64;
    int npts = N - base; if (npts > 64) npts = 64;
    int tot = npts * 27;
    for (int e = threadIdx.x; e < tot; e += blockDim.x)
        tile[e] = idx2[(size_t)base * 27 + e];
    __syncthreads();
    for (int e = threadIdx.x; e < 27 * 64; e += blockDim.x) {
        int k = e >> 6, ii = e & 63;
        if (ii < npts) idxT[(size_t)k * N + base + ii] = tile[ii * 27 + k];
    }
}

// ---------------------------------------------------------------------------
// Pair-list construction, VECTORIZED (4 elements/thread, int4 loads) with
// BLOCK-AGGREGATED atomics.
// ---------------------------------------------------------------------------
__global__ void k_build1(const int* __restrict__ idx, int total) {  // total = N*27
    __shared__ int scnt[27];
    __shared__ int sbase[27];
    int tid = threadIdx.x;
    if (tid < 27) scnt[tid] = 0;
    __syncthreads();

    int e0 = (blockIdx.x * blockDim.x + tid) * 4;
    int4 v = make_int4(-1, -1, -1, -1);
    if (e0 + 3 < total) {
        v = *(const int4*)(idx + e0);
    } else {
        if (e0 + 0 < total) v.x = idx[e0 + 0];
        if (e0 + 1 < total) v.y = idx[e0 + 1];
        if (e0 + 2 < total) v.z = idx[e0 + 2];
        if (e0 + 3 < total) v.w = idx[e0 + 3];
    }
    int jj[4] = {v.x, v.y, v.z, v.w};
    int km[4], im[4], rm[4];
#pragma unroll
    for (int m = 0; m < 4; m++) {
        int e = e0 + m;
        int kk = e % 27;
        km[m] = -1;
        if (kk != 13 && jj[m] >= 0) {     // center offset handled densely
            km[m] = kk; im[m] = e / 27;
            rm[m] = atomicAdd(&scnt[kk], 1);
        }
    }
    __syncthreads();
    if (tid < 27 && scnt[tid] > 0)
        sbase[tid] = atomicAdd(&g_cnt1[tid], scnt[tid]);
    __syncthreads();
#pragma unroll
    for (int m = 0; m < 4; m++)
        if (km[m] >= 0)
            g_pairs1[(size_t)km[m] * NMAX + sbase[km[m]] + rm[m]] = make_int2(im[m], jj[m]);
}

__global__ void k_buildd(const int* __restrict__ idx, int total) {  // total = N2*8
    __shared__ int scnt[8];
    __shared__ int sbase[8];
    int tid = threadIdx.x;
    if (tid < 8) scnt[tid] = 0;
    __syncthreads();

    int e0 = (blockIdx.x * blockDim.x + tid) * 4;
    int4 v = make_int4(-1, -1, -1, -1);
    if (e0 + 3 < total) {
        v = *(const int4*)(idx + e0);
    } else {
        if (e0 + 0 < total) v.x = idx[e0 + 0];
        if (e0 + 1 < total) v.y = idx[e0 + 1];
        if (e0 + 2 < total) v.z = idx[e0 + 2];
        if (e0 + 3 < total) v.w = idx[e0 + 3];
    }
    int jj[4] = {v.x, v.y, v.z, v.w};
    int km[4], im[4], rm[4];
#pragma unroll
    for (int m = 0; m < 4; m++) {
        int e = e0 + m;
        km[m] = -1;
        if (jj[m] >= 0) {
            km[m] = e & 7; im[m] = e >> 3;
            rm[m] = atomicAdd(&scnt[km[m]], 1);
        }
    }
    __syncthreads();
    if (tid < 8 && scnt[tid] > 0)
        sbase[tid] = atomicAdd(&g_cntd[tid], scnt[tid]);
    __syncthreads();
#pragma unroll
    for (int m = 0; m < 4; m++)
        if (km[m] >= 0)
            g_pairsd[(size_t)km[m] * NMAX + sbase[km[m]] + rm[m]] = make_int2(im[m], jj[m]);
}

// ---------------------------------------------------------------------------
// conv1 center offset (k==13, identity map): F1 = X @ W13 + b1  (dense GEMM)
// ---------------------------------------------------------------------------
__global__ void k_conv1_center(const float* __restrict__ W, const float* __restrict__ b1,
                               const float* __restrict__ src, float* __restrict__ dst, int N) {
    __shared__ __align__(16) float xs[64][68];
    __shared__ __align__(16) float ws[64][68];
    int tid = threadIdx.x;
    int base = blockIdx.x * 64;

    const float4* W4 = (const float4*)(W + 13 * 4096);
    for (int f = tid; f < 1024; f += 256) {
        int c = f >> 4, oq = f & 15;
        *(float4*)&ws[c][oq * 4] = W4[f];
    }
    int r = tid & 63, cg = tid >> 6;
#pragma unroll
    for (int m = 0; m < 4; m++) {
        int cc = cg * 4 + m;
        float4 v = make_float4(0.f, 0.f, 0.f, 0.f);
        if (base + r < N) v = ((const float4*)src)[(size_t)(base + r) * 16 + cc];
        xs[cc * 4 + 0][r] = v.x; xs[cc * 4 + 1][r] = v.y;
        xs[cc * 4 + 2][r] = v.z; xs[cc * 4 + 3][r] = v.w;
    }
    __syncthreads();

    int p0 = (tid & 15) * 4, o0 = (tid >> 4) * 4;
    u64 acc2[4][2] = {};
#pragma unroll 8
    for (int c = 0; c < 64; c++) {
        float4 a = *(float4*)&xs[c][p0];
        u64 w01 = *(const u64*)&ws[c][o0];
        u64 w23 = *(const u64*)&ws[c][o0 + 2];
        float ap[4] = {a.x, a.y, a.z, a.w};
#pragma unroll
        for (int p = 0; p < 4; p++) {
            u64 ad = pack2(ap[p], ap[p]);
            acc2[p][0] = fma2(ad, w01, acc2[p][0]);
            acc2[p][1] = fma2(ad, w23, acc2[p][1]);
        }
    }
    float4 bb = ((const float4*)b1)[o0 >> 2];
#pragma unroll
    for (int p = 0; p < 4; p++) {
        int i = base + p0 + p;
        if (i < N) {
            float a0, a1, a2, a3;
            unpack2(acc2[p][0], a0, a1);
            unpack2(acc2[p][1], a2, a3);
            float4 o = make_float4(a0 + bb.x, a1 + bb.y, a2 + bb.z, a3 + bb.w);
            ((float4*)dst)[(size_t)i * 16 + (o0 >> 2)] = o;
        }
    }
}

// ---------------------------------------------------------------------------
// PERSISTENT pair-compacted gather-GEMM. PIPE selects register-prefetch
// software pipelining (good for COUT=64's long compute body; bad for COUT=32).
// ---------------------------------------------------------------------------
template <int COUT, int NK, bool RELU_SRC, bool PIPE>
__global__ void __launch_bounds__(128, 4)
k_pair_gemm_p(const float* __restrict__ W, const int2* __restrict__ pairsBase,
              const int* __restrict__ cntArr,
              const float* __restrict__ src, float* __restrict__ dst) {
    constexpr int CT = COUT / 8;          // couts per thread: 64->8, 32->4
    __shared__ __align__(16) float xs[64][68];
    __shared__ __align__(16) float ws[64][COUT + 4];
    __shared__ int sdst[64];
    __shared__ int ssrc[64];
    __shared__ int spre[NK + 1];
    __shared__ int scnt[NK];

    int tid = threadIdx.x;
    if (tid < NK) scnt[tid] = cntArr[tid];
    __syncthreads();
    if (tid == 0) {
        int s = 0;
        for (int k = 0; k < NK; k++) { spre[k] = s; s += (scnt[k] + 63) >> 6; }
        spre[NK] = s;
    }
    __syncthreads();

    int total = spre[NK];
    int chunk = (total + gridDim.x - 1) / gridDim.x;
    int tile  = blockIdx.x * chunk;
    int tEnd  = min(tile + chunk, total);
    if (tile >= tEnd) return;

    int pg = tid & 15, og = tid >> 4;     // 16 pair-groups x 8 chan-groups
    int p0 = pg * 4, o0 = og * CT;
    int row0 = tid >> 2, cl = tid & 3;    // gather rows row0, row0+32

    int kcur = 0;
    while (spre[kcur + 1] <= tile) kcur++;
    int kprev = -1;

    if (PIPE) {
        float4 v0[4], v1[4];
        int dpre;
        {
            int t0 = (tile - spre[kcur]) * 64;
            int n  = scnt[kcur];
            const int2* pb = pairsBase + (size_t)kcur * NMAX + t0;
            int j0 = (t0 + row0      < n) ? pb[row0].y      : -1;
            int j1 = (t0 + row0 + 32 < n) ? pb[row0 + 32].y : -1;
            dpre = (tid < 64 && t0 + tid < n) ? pb[tid].x : -1;
            const float4* s0 = (j0 >= 0) ? ((const float4*)src) + (size_t)j0 * 16 : nullptr;
            const float4* s1 = (j1 >= 0) ? ((const float4*)src) + (size_t)j1 * 16 : nullptr;
#pragma unroll
            for (int m = 0; m < 4; m++) {
                int col = cl + m * 4;
                float4 a = make_float4(0.f, 0.f, 0.f, 0.f), bb = a;
                if (s0) a  = s0[col];
                if (s1) bb = s1[col];
                v0[m] = a; v1[m] = bb;
            }
        }

        for (;;) {
            __syncthreads();
            if (kcur != kprev) {
                const float4* W4 = (const float4*)(W + (size_t)kcur * 64 * COUT);
                for (int f = tid; f < 64 * COUT / 4; f += 128) {
                    int c = f / (COUT / 4), oq = f % (COUT / 4);
                    *(float4*)&ws[c][oq * 4] = W4[f];
                }
                kprev = kcur;
            }
#pragma unroll
            for (int m = 0; m < 4; m++) {
                int c = (cl + m * 4) * 4;
                xs[c + 0][row0] = v0[m].x; xs[c + 1][row0] = v0[m].y;
                xs[c + 2][row0] = v0[m].z; xs[c + 3][row0] = v0[m].w;
                xs[c + 0][row0 + 32] = v1[m].x; xs[c + 1][row0 + 32] = v1[m].y;
                xs[c + 2][row0 + 32] = v1[m].z; xs[c + 3][row0 + 32] = v1[m].w;
            }
            if (tid < 64) sdst[tid] = dpre;
            __syncthreads();

            int tnext = tile + 1;
            bool more = (tnext < tEnd);
            int knext = kcur;
            if (more) {
                while (spre[knext + 1] <= tnext) knext++;
                int t0 = (tnext - spre[knext]) * 64;
                int n  = scnt[knext];
                const int2* pb = pairsBase + (size_t)knext * NMAX + t0;
                int j0 = (t0 + row0      < n) ? pb[row0].y      : -1;
                int j1 = (t0 + row0 + 32 < n) ? pb[row0 + 32].y : -1;
                dpre = (tid < 64 && t0 + tid < n) ? pb[tid].x : -1;
                const float4* s0 = (j0 >= 0) ? ((const float4*)src) + (size_t)j0 * 16 : nullptr;
                const float4* s1 = (j1 >= 0) ? ((const float4*)src) + (size_t)j1 * 16 : nullptr;
#pragma unroll
                for (int m = 0; m < 4; m++) {
                    int col = cl + m * 4;
                    float4 a = make_float4(0.f, 0.f, 0.f, 0.f), bb = a;
                    if (s0) a  = s0[col];
                    if (s1) bb = s1[col];
                    v0[m] = a; v1[m] = bb;
                }
            }

            u64 acc2[4][CT / 2] = {};
#pragma unroll 8
            for (int c = 0; c < 64; c++) {
                u64 wq[CT / 2];
                if (CT == 8) {
                    ulonglong2 wA = *(const ulonglong2*)&ws[c][o0];
                    ulonglong2 wB = *(const ulonglong2*)&ws[c][o0 + 4];
                    wq[0] = wA.x; wq[1] = wA.y; wq[2] = wB.x; wq[3] = wB.y;
                } else {
                    ulonglong2 wA = *(const ulonglong2*)&ws[c][o0];
                    wq[0] = wA.x; wq[1] = wA.y;
                }
                float4 a4 = *(float4*)&xs[c][p0];
                float a[4] = {a4.x, a4.y, a4.z, a4.w};
#pragma unroll
                for (int p = 0; p < 4; p++) {
                    u64 ad = pack2(a[p], a[p]);
#pragma unroll
                    for (int q = 0; q < CT / 2; q++)
                        acc2[p][q] = fma2(ad, wq[q], acc2[p][q]);
                }
            }
#pragma unroll
            for (int p = 0; p < 4; p++) {
                int d = sdst[p0 + p];
                if (d >= 0) {
#pragma unroll
                    for (int h = 0; h < CT / 4; h++) {
                        float4 v;
                        unpack2(acc2[p][h * 2 + 0], v.x, v.y);
                        unpack2(acc2[p][h * 2 + 1], v.z, v.w);
                        red_add_v4(&dst[(size_t)d * COUT + o0 + h * 4], v);
                    }
                }
            }

            if (!more) break;
            tile = tnext; kcur = knext;
        }
    } else {
        for (; tile < tEnd; ++tile) {
            while (spre[kcur + 1] <= tile) kcur++;

            __syncthreads();
            if (kcur != kprev) {
                const float4* W4 = (const float4*)(W + (size_t)kcur * 64 * COUT);
                for (int f = tid; f < 64 * COUT / 4; f += 128) {
                    int c = f / (COUT / 4), oq = f % (COUT / 4);
                    *(float4*)&ws[c][oq * 4] = W4[f];
                }
                kprev = kcur;
            }
            int t0 = (tile - spre[kcur]) * 64;
            int n  = scnt[kcur];
            if (tid < 64) {
                int2 pr = make_int2(-1, -1);
                if (t0 + tid < n) pr = pairsBase[(size_t)kcur * NMAX + t0 + tid];
                sdst[tid] = pr.x; ssrc[tid] = pr.y;
            }
            __syncthreads();

#pragma unroll
            for (int pass = 0; pass < 2; pass++) {
                int row = row0 + pass * 32;
                int j = ssrc[row];
                const float4* srow = (j >= 0) ? ((const float4*)src) + (size_t)j * 16 : nullptr;
#pragma unroll
                for (int m = 0; m < 4; m++) {
                    int col = cl + m * 4;
                    float4 v = make_float4(0.f, 0.f, 0.f, 0.f);
                    if (srow) v = srow[col];
                    if (RELU_SRC) {
                        v.x = fmaxf(v.x, 0.f); v.y = fmaxf(v.y, 0.f);
                        v.z = fmaxf(v.z, 0.f); v.w = fmaxf(v.w, 0.f);
                    }
                    int c = col * 4;
                    xs[c + 0][row] = v.x; xs[c + 1][row] = v.y;
                    xs[c + 2][row] = v.z; xs[c + 3][row] = v.w;
                }
            }
            __syncthreads();

            u64 acc2[4][CT / 2] = {};
#pragma unroll 8
            for (int c = 0; c < 64; c++) {
                u64 wq[CT / 2];
                if (CT == 8) {
                    ulonglong2 wA = *(const ulonglong2*)&ws[c][o0];
                    ulonglong2 wB = *(const ulonglong2*)&ws[c][o0 + 4];
                    wq[0] = wA.x; wq[1] = wA.y; wq[2] = wB.x; wq[3] = wB.y;
                } else {
                    ulonglong2 wA = *(const ulonglong2*)&ws[c][o0];
                    wq[0] = wA.x; wq[1] = wA.y;
                }
                float4 a4 = *(float4*)&xs[c][p0];
                float a[4] = {a4.x, a4.y, a4.z, a4.w};
#pragma unroll
                for (int p = 0; p < 4; p++) {
                    u64 ad = pack2(a[p], a[p]);
#pragma unroll
                    for (int q = 0; q < CT / 2; q++)
                        acc2[p][q] = fma2(ad, wq[q], acc2[p][q]);
                }
            }
#pragma unroll
            for (int p = 0; p < 4; p++) {
                int d = sdst[p0 + p];
                if (d >= 0) {
#pragma unroll
                    for (int h = 0; h < CT / 4; h++) {
                        float4 v;
                        unpack2(acc2[p][h * 2 + 0], v.x, v.y);
                        unpack2(acc2[p][h * 2 + 1], v.z, v.w);
                        red_add_v4(&dst[(size_t)d * COUT + o0 + h * 4], v);
                    }
                }
            }
        }
    }
}

// ---------------------------------------------------------------------------
// Warp-split 27-offset conv, CIN=32 -> COUT=8 (round-12 proven form, PB=4).
// FROZEN: rounds 4/11/13 all failed to improve this kernel's structure.
// ---------------------------------------------------------------------------
template <bool RELU>
__global__ void __launch_bounds__(128)
k_conv27W(const float* __restrict__ feat, const int* __restrict__ idxT,
          const float* __restrict__ W, const float* __restrict__ b,
          float* __restrict__ out, int N) {
    __shared__ __align__(16) u64 wsm[27 * 8 * 4 * 4];  // 3456 u64 = 27.6 KB
    __shared__ float sbv[8];
    int tid = threadIdx.x;

    for (int f = tid; f < 3456; f += 128) {
        int k = f >> 7, r = f & 127;
        int cc = r >> 4, q = (r >> 2) & 3, op = r & 3;
        float2 w2 = *(const float2*)&W[k * 256 + (q * 8 + cc) * 8 + op * 2];
        wsm[f] = pack2(w2.x, w2.y);
    }
    if (tid < 8) sbv[tid] = b[tid];
    __syncthreads();

    int q = tid & 3, pb = tid >> 2;
    int i0 = blockIdx.x * 128 + pb;      // points i0, i0+32, i0+64, i0+96

    u64 acc[4][4] = {};

    for (int k = 0; k < 27; k++) {
        const int* ik = idxT + (size_t)k * N;
        int j[4];
#pragma unroll
        for (int p = 0; p < 4; p++) {
            int i = i0 + p * 32;
            j[p] = (i < N) ? ik[i] : -1;
        }
        bool any = (j[0] >= 0) | (j[1] >= 0) | (j[2] >= 0) | (j[3] >= 0);
        if (__ballot_sync(0xFFFFFFFFu, any) == 0) continue;

        float fr[4][8];
#pragma unroll
        for (int p = 0; p < 4; p++) {
            float4 A = make_float4(0.f, 0.f, 0.f, 0.f), B = A;
            if (j[p] >= 0) {
                const float4* fp = (const float4*)(feat + (size_t)j[p] * 32 + q * 8);
                A = fp[0]; B = fp[1];
            }
            fr[p][0] = A.x; fr[p][1] = A.y; fr[p][2] = A.z; fr[p][3] = A.w;
            fr[p][4] = B.x; fr[p][5] = B.y; fr[p][6] = B.z; fr[p][7] = B.w;
        }

        const u64* wkq = wsm + k * 128 + q * 4;
#pragma unroll
        for (int cc = 0; cc < 8; cc++) {
            const ulonglong2* wp = (const ulonglong2*)(wkq + cc * 16);
            ulonglong2 wA = wp[0];          // out pairs (0,1),(2,3)
            ulonglong2 wB = wp[1];          // out pairs (4,5),(6,7)
#pragma unroll
            for (int p = 0; p < 4; p++) {
                u64 ad = pack2(fr[p][cc], fr[p][cc]);
                acc[p][0] = fma2(ad, wA.x, acc[p][0]);
                acc[p][1] = fma2(ad, wA.y, acc[p][1]);
                acc[p][2] = fma2(ad, wB.x, acc[p][2]);
                acc[p][3] = fma2(ad, wB.y, acc[p][3]);
            }
        }
    }

    // reduce across the 4 q-lanes of each point (consecutive lanes)
#pragma unroll
    for (int p = 0; p < 4; p++) {
#pragma unroll
        for (int m = 0; m < 4; m++) {
            u64 o1 = __shfl_down_sync(0xFFFFFFFFu, acc[p][m], 1, 4);
            acc[p][m] = add2(acc[p][m], o1);
            u64 o2 = __shfl_down_sync(0xFFFFFFFFu, acc[p][m], 2, 4);
            acc[p][m] = add2(acc[p][m], o2);
        }
    }

    if (q == 0) {
#pragma unroll
        for (int p = 0; p < 4; p++) {
            int i = i0 + p * 32;
            if (i < N) {
                float t[8];
                unpack2(acc[p][0], t[0], t[1]);
                unpack2(acc[p][1], t[2], t[3]);
                unpack2(acc[p][2], t[4], t[5]);
                unpack2(acc[p][3], t[6], t[7]);
#pragma unroll
                for (int o = 0; o < 8; o++) {
                    float x = t[o] + sbv[o];
                    if (RELU) x = fmaxf(x, 0.0f);
                    t[o] = x;
                }
                float* op = out + (size_t)i * 8;
                ((float4*)op)[0] = make_float4(t[0], t[1], t[2], t[3]);
                ((float4*)op)[1] = make_float4(t[4], t[5], t[6], t[7]);
            }
        }
    }
}

// ---------------------------------------------------------------------------
// Dense-k 27-offset conv, small CIN (=8) — TRANSPOSED idx access (coalesced
// per-k index stream; only the address arithmetic differs from round-15).
// ---------------------------------------------------------------------------
template <int CIN, int COUT, int PT, bool RELU, bool RES>
__global__ void k_conv27(const float* __restrict__ feat, const int* __restrict__ idxT,
                         const float* __restrict__ W, const float* __restrict__ b,
                         const float* __restrict__ res, float* __restrict__ out,
                         int outStride, int outOff, int N) {
    __shared__ __align__(16) float ws[27 * CIN * COUT];
    __shared__ float sb[COUT];
    int tid = threadIdx.x;
    for (int f = tid; f < 27 * CIN * COUT; f += blockDim.x) ws[f] = W[f];
    if (tid < COUT) sb[tid] = b[tid];
    __syncthreads();

    int i0 = (blockIdx.x * blockDim.x + tid) * PT;

    u64 acc[PT][COUT / 2] = {};

    for (int k = 0; k < 27; k++) {
        const int* ik = idxT + (size_t)k * N;
        int jj[PT];
#pragma unroll
        for (int p = 0; p < PT; p++) {
            int i = i0 + p;
            jj[p] = (i < N) ? ik[i] : -1;
        }
        const float* wk = &ws[k * CIN * COUT];
#pragma unroll
        for (int c4 = 0; c4 < CIN / 4; c4++) {
            float vv[PT][4];
#pragma unroll
            for (int p = 0; p < PT; p++) {
                float4 v = make_float4(0.f, 0.f, 0.f, 0.f);
                if (jj[p] >= 0) v = ((const float4*)feat)[(size_t)jj[p] * (CIN / 4) + c4];
                vv[p][0] = v.x; vv[p][1] = v.y; vv[p][2] = v.z; vv[p][3] = v.w;
            }
#pragma unroll
            for (int cc = 0; cc < 4; cc++) {
                const u64* w2 = (const u64*)&wk[(c4 * 4 + cc) * COUT];
                u64 wq[COUT / 2];
#pragma unroll
                for (int qq = 0; qq < COUT / 2; qq++) wq[qq] = w2[qq];
#pragma unroll
                for (int p = 0; p < PT; p++) {
                    u64 ad = pack2(vv[p][cc], vv[p][cc]);
#pragma unroll
                    for (int qq = 0; qq < COUT / 2; qq++)
                        acc[p][qq] = fma2(ad, wq[qq], acc[p][qq]);
                }
            }
        }
    }

#pragma unroll
    for (int p = 0; p < PT; p++) {
        int i = i0 + p;
        if (i < N) {
            float tmp[COUT];
#pragma unroll
            for (int qq = 0; qq < COUT / 2; qq++)
                unpack2(acc[p][qq], tmp[2 * qq], tmp[2 * qq + 1]);
#pragma unroll
            for (int o = 0; o < COUT; o++) {
                float x = tmp[o] + sb[o];
                if (RELU) x = fmaxf(x, 0.0f);
                tmp[o] = x;
            }
            float* op = out + (size_t)i * outStride + outOff;
            const float* rp = RES ? (res + (size_t)i * 32 + outOff) : nullptr;
#pragma unroll
            for (int qq = 0; qq < COUT / 4; qq++) {
                float4 t4 = make_float4(tmp[qq * 4 + 0], tmp[qq * 4 + 1],
                                        tmp[qq * 4 + 2], tmp[qq * 4 + 3]);
                if (RES) {
                    float4 r4 = ((const float4*)rp)[qq];
                    t4.x += r4.x; t4.y += r4.y; t4.z += r4.z; t4.w += r4.w;
                }
                ((float4*)op)[qq] = t4;
            }
        }
    }
}

// ---------------------------------------------------------------------------
// FUSED conv27 (8->8, relu) + pointwise (8->16) + bias + residual (EPILOGUE
// fusion; TRANSPOSED idx access — only address arithmetic differs):
//   Fn[i, 16:32] = relu(conv27(T8, W11)+B11) @ W12 + B12 + F[i, 16:32]
// ---------------------------------------------------------------------------
template <int PT>
__global__ void k_conv27_pw8(const float* __restrict__ feat, const int* __restrict__ idxT,
                             const float* __restrict__ W, const float* __restrict__ b,
                             const float* __restrict__ W12, const float* __restrict__ b12,
                             const float* __restrict__ res, float* __restrict__ out, int N) {
    __shared__ __align__(16) float ws[27 * 64];      // 27x8x8 conv weights
    __shared__ __align__(16) u64 w12p[64];           // 8x16 pw weights, paired
    __shared__ float sb[8];
    __shared__ float sb12[16];
    int tid = threadIdx.x;
    for (int f = tid; f < 27 * 64; f += blockDim.x) ws[f] = W[f];
    if (tid < 64) {
        int c = tid >> 3, op = tid & 7;
        float2 w2 = *(const float2*)&W12[c * 16 + op * 2];
        w12p[tid] = pack2(w2.x, w2.y);
    }
    if (tid < 8)  sb[tid] = b[tid];
    if (tid < 16) sb12[tid] = b12[tid];
    __syncthreads();

    int i0 = (blockIdx.x * blockDim.x + tid) * PT;

    u64 acc[PT][4] = {};

    for (int k = 0; k < 27; k++) {
        const int* ik = idxT + (size_t)k * N;
        int jj[PT];
#pragma unroll
        for (int p = 0; p < PT; p++) {
            int i = i0 + p;
            jj[p] = (i < N) ? ik[i] : -1;
        }
        const float* wk = &ws[k * 64];
#pragma unroll
        for (int c4 = 0; c4 < 2; c4++) {
            float vv[PT][4];
#pragma unroll
            for (int p = 0; p < PT; p++) {
                float4 v = make_float4(0.f, 0.f, 0.f, 0.f);
                if (jj[p] >= 0) v = ((const float4*)feat)[(size_t)jj[p] * 2 + c4];
                vv[p][0] = v.x; vv[p][1] = v.y; vv[p][2] = v.z; vv[p][3] = v.w;
            }
#pragma unroll
            for (int cc = 0; cc < 4; cc++) {
                const u64* w2 = (const u64*)&wk[(c4 * 4 + cc) * 8];
                u64 wq[4];
#pragma unroll
                for (int qq = 0; qq < 4; qq++) wq[qq] = w2[qq];
#pragma unroll
                for (int p = 0; p < PT; p++) {
                    u64 ad = pack2(vv[p][cc], vv[p][cc]);
#pragma unroll
                    for (int qq = 0; qq < 4; qq++)
                        acc[p][qq] = fma2(ad, wq[qq], acc[p][qq]);
                }
            }
        }
    }

#pragma unroll
    for (int p = 0; p < PT; p++) {
        int i = i0 + p;
        if (i < N) {
            float tmp[8];
#pragma unroll
            for (int qq = 0; qq < 4; qq++)
                unpack2(acc[p][qq], tmp[2 * qq], tmp[2 * qq + 1]);
#pragma unroll
            for (int o = 0; o < 8; o++)
                tmp[o] = fmaxf(tmp[o] + sb[o], 0.0f);

            // pointwise 8->16 (epilogue registers only)
            u64 opw[8] = {};
#pragma unroll
            for (int cc = 0; cc < 8; cc++) {
                u64 ad = pack2(tmp[cc], tmp[cc]);
                const u64* wrow = w12p + cc * 8;
#pragma unroll
                for (int jq = 0; jq < 8; jq++)
                    opw[jq] = fma2(ad, wrow[jq], opw[jq]);
            }
            float o16[16];
#pragma unroll
            for (int jq = 0; jq < 8; jq++)
                unpack2(opw[jq], o16[2 * jq], o16[2 * jq + 1]);

            float* op = out + (size_t)i * 32 + 16;
            const float* rp = res + (size_t)i * 32 + 16;
#pragma unroll
            for (int qq = 0; qq < 4; qq++) {
                float4 r4 = ((const float4*)rp)[qq];
                float4 t4 = make_float4(o16[qq * 4 + 0] + sb12[qq * 4 + 0] + r4.x,
                                        o16[qq * 4 + 1] + sb12[qq * 4 + 1] + r4.y,
                                        o16[qq * 4 + 2] + sb12[qq * 4 + 2] + r4.z,
                                        o16[qq * 4 + 3] + sb12[qq * 4 + 3] + r4.w);
                ((float4*)op)[qq] = t4;
            }
        }
    }
}

// ---------------------------------------------------------------------------
// Pointwise (kernel-size-1) conv: out = (relu?)(feat @ W + b) (+ res)
// ---------------------------------------------------------------------------
template <int CIN, int COUT, bool RELU, bool RES>
__global__ void k_pw(const float* __restrict__ feat, const float* __restrict__ W,
                     const float* __restrict__ b, const float* __restrict__ res,
                     float* __restrict__ out, int outStride, int outOff, int N) {
    __shared__ __align__(16) float ws[CIN * COUT];
    __shared__ float sb[COUT];
    int tid = threadIdx.x;
    for (int f = tid; f < CIN * COUT; f += blockDim.x) ws[f] = W[f];
    if (tid < COUT) sb[tid] = b[tid];
    __syncthreads();

    int i = blockIdx.x * blockDim.x + tid;
    if (i >= N) return;

    u64 acc[COUT / 2] = {};

#pragma unroll
    for (int c4 = 0; c4 < CIN / 4; c4++) {
        float4 v = ((const float4*)feat)[(size_t)i * (CIN / 4) + c4];
        float vv[4] = {v.x, v.y, v.z, v.w};
#pragma unroll
        for (int cc = 0; cc < 4; cc++) {
            const u64* w2 = (const u64*)&ws[(c4 * 4 + cc) * COUT];
            u64 ad = pack2(vv[cc], vv[cc]);
#pragma unroll
            for (int qq = 0; qq < COUT / 2; qq++)
                acc[qq] = fma2(ad, w2[qq], acc[qq]);
        }
    }

    float tmp[COUT];
#pragma unroll
    for (int qq = 0; qq < COUT / 2; qq++)
        unpack2(acc[qq], tmp[2 * qq], tmp[2 * qq + 1]);

    float* op = out + (size_t)i * outStride + outOff;
#pragma unroll
    for (int qq = 0; qq < COUT / 4; qq++) {
        float4 t4 = make_float4(tmp[qq * 4 + 0] + sb[qq * 4 + 0], tmp[qq * 4 + 1] + sb[qq * 4 + 1],
                                tmp[qq * 4 + 2] + sb[qq * 4 + 2], tmp[qq * 4 + 3] + sb[qq * 4 + 3]);
        if (RELU) {
            t4.x = fmaxf(t4.x, 0.f); t4.y = fmaxf(t4.y, 0.f);
            t4.z = fmaxf(t4.z, 0.f); t4.w = fmaxf(t4.w, 0.f);
        }
        if (RES) {
            float4 r4 = ((const float4*)(res + (size_t)i * 32 + outOff))[qq];
            t4.x += r4.x; t4.y += r4.y; t4.z += r4.z; t4.w += r4.w;
        }
        ((float4*)op)[qq] = t4;
    }
}

// ---------------------------------------------------------------------------
// Host launcher
// ---------------------------------------------------------------------------
extern "C" void kernel_launch(void* const* d_in, const int* in_sizes, int n_in,
                              void* d_out, int out_size) {
    const float* x_feat = (const float*)d_in[0];
    const float* f1_ref = (const float*)d_in[1];
    const float* w1     = (const float*)d_in[2];
    const float* b1     = (const float*)d_in[3];
    const float* wd     = (const float*)d_in[4];
    const float* bd     = (const float*)d_in[5];
    const float* rw00   = (const float*)d_in[6];
    const float* rb00   = (const float*)d_in[7];
    const float* rw01   = (const float*)d_in[8];
    const float* rb01   = (const float*)d_in[9];
    const float* rw10   = (const float*)d_in[10];
    const float* rb10   = (const float*)d_in[11];
    const float* rw11   = (const float*)d_in[12];
    const float* rb11   = (const float*)d_in[13];
    const float* rw12   = (const float*)d_in[14];
    const float* rb12   = (const float*)d_in[15];
    const float* w4     = (const float*)d_in[16];
    const float* b4     = (const float*)d_in[17];
    const int*   idx1   = (const int*)d_in[18];
    const int*   idxd   = (const int*)d_in[19];
    const int*   idx2   = (const int*)d_in[20];
    float* outp = (float*)d_out;

    int N  = in_sizes[0] / 64;
    int N2 = in_sizes[19] / 8;

    float *pX, *pF1, *pF2a, *pF2b, *pA8, *pT8;
    int *pCnt1, *pCntd, *pIdxT;
    int2 *pPairs1, *pPairsd;
    cudaGetSymbolAddress((void**)&pX, g_X);
    cudaGetSymbolAddress((void**)&pF1, g_F1);
    cudaGetSymbolAddress((void**)&pF2a, g_F2a);
    cudaGetSymbolAddress((void**)&pF2b, g_F2b);
    cudaGetSymbolAddress((void**)&pA8, g_A8);
    cudaGetSymbolAddress((void**)&pT8, g_T8);
    cudaGetSymbolAddress((void**)&pCnt1, g_cnt1);
    cudaGetSymbolAddress((void**)&pCntd, g_cntd);
    cudaGetSymbolAddress((void**)&pPairs1, g_pairs1);
    cudaGetSymbolAddress((void**)&pPairsd, g_pairsd);
    cudaGetSymbolAddress((void**)&pIdxT, g_idxT);

    // 0: residual add (also zeroes pair counters)
    {
        int n4 = N * 16;
        k_add<<<(n4 + 255) / 256, 256>>>((const float4*)x_feat, (const float4*)f1_ref,
                                         (float4*)pX, n4);
    }
    // 1: conv1 pair lists (vectorized, 4 elem/thread)
    {
        int total = N * 27;
        int thr = (total + 3) / 4;
        k_build1<<<(thr + 255) / 256, 256>>>(idx1, total);
    }
    // 2: conv1 center (dense GEMM, non-atomic init of F1 with bias)
    k_conv1_center<<<(N + 63) / 64, 256>>>(w1, b1, pX, pF1, N);
    // 3: conv1 offset GEMMs — persistent PIPELINED   <- profiled slot
    k_pair_gemm_p<64, 27, false, true><<<GP_BLOCKS, 128>>>(w1, pPairs1, pCnt1, pX, pF1);
    // 4: downsample pair lists (vectorized)
    {
        int total = N2 * 8;
        int thr = (total + 3) / 4;
        k_buildd<<<(thr + 255) / 256, 256>>>(idxd, total);
    }
    // 5: transpose idx2 for coalesced per-k loads (all dense-k convs)
    k_tidx<<<(N2 + 63) / 64, 256>>>(idx2, pIdxT, N2);

    // down conv (k2/s2): init with bias, persistent NON-pipelined pair GEMM, relu
    k_bias_init32<<<(N2 * 32 + 255) / 256, 256>>>(pF2a, bd, N2 * 32);
    k_pair_gemm_p<32, 8, true, false><<<GP_BLOCKS, 128>>>(wd, pPairsd, pCntd, pF1, pF2a);
    k_relu<<<(N2 * 32 + 255) / 256, 256>>>(pF2a, N2 * 32);

    // --- 3 InceptionResNet blocks (4 launches each) ---
    int gW = (N2 + 127) / 128;          // PB=4: 128 points/block (round-12 form)
    float* F  = pF2a;
    float* Fn = pF2b;
    for (int i = 0; i < 3; i++) {
        const float* W00 = rw00 + (size_t)i * 27 * 32 * 8;
        const float* B00 = rb00 + (size_t)i * 8;
        const float* W01 = rw01 + (size_t)i * 27 * 8 * 16;
        const float* B01 = rb01 + (size_t)i * 16;
        const float* W10 = rw10 + (size_t)i * 32 * 8;
        const float* B10 = rb10 + (size_t)i * 8;
        const float* W11 = rw11 + (size_t)i * 27 * 8 * 8;
        const float* B11 = rb11 + (size_t)i * 8;
        const float* W12 = rw12 + (size_t)i * 8 * 16;
        const float* B12 = rb12 + (size_t)i * 16;

        // A8 = relu(conv27(F, rw00))          [32 -> 8]  warp-split, PB=4
        k_conv27W<true><<<gW, 128>>>(F, pIdxT, W00, B00, pA8, N2);
        // Fn[:, 0:16] = conv27(A8, rw01) + F[:, 0:16]   [8 -> 16]  (idxT)
        k_conv27<8, 16, 2, false, true><<<(N2 + 255) / 256, 128>>>(
            pA8, pIdxT, W01, B01, F, Fn, 32, 0, N2);
        // T8 = relu(F @ rw10 + b)             [32 -> 8]
        k_pw<32, 8, true, false><<<(N2 + 127) / 128, 128>>>(
            F, W10, B10, nullptr, pT8, 8, 0, N2);
        // Fn[:, 16:32] = relu(conv27(T8, rw11)) @ rw12 + b + F[:, 16:32] [fused, idxT]
        k_conv27_pw8<4><<<(N2 + 511) / 512, 128>>>(
            pT8, pIdxT, W11, B11, W12, B12, F, Fn, N2);

        float* t = F; F = Fn; Fn = t;
    }

    // --- enc4: conv27(F, w4) + b4 -> output  [32 -> 8]  warp-split, PB=4 ---
    k_conv27W<false><<<gW, 128>>>(F, pIdxT, w4, b4, outp, N2);
}